// round 4
// baseline (speedup 1.0000x reference)
#include <cuda_runtime.h>

#define NGRAPH 16
#define NODESP 420
#define NN     6720
#define NEDGE  53760
#define INDIM  2048
#define C1     2048   // HEADS*H1
#define H1     1024
#define H2     64
#define OUTD   18
#define FCK    26880  // 420*64

// ---------------- device scratch (module-load global, no runtime allocation) ----------------
__device__ float g_h[NN * INDIM];
__device__ float g_q1[NN * C1];
__device__ float g_k1[NN * C1];
__device__ float g_v1[NN * C1];
__device__ float g_s1[NN * C1];
__device__ float g_att1[NN * C1];
__device__ float g_out1[NN * C1];
__device__ float g_al1[NEDGE * 2];
__device__ float g_dn1[NN * 2];
__device__ float g_q2[NN * H2];
__device__ float g_k2[NN * H2];
__device__ float g_v2[NN * H2];
__device__ float g_s2[NN * H2];
__device__ float g_att2[NN * H2];
__device__ float g_out2[NN * H2];
__device__ float g_al2[NEDGE];
__device__ float g_dn2[NN];
__device__ float g_f1[NGRAPH * 256];
__device__ float g_f2[NGRAPH * 128];
__device__ float g_f3[NGRAPH * 64];
__device__ int   g_src[NEDGE];
__device__ int   g_dst[NEDGE];
__device__ int   g_conn[NN];

// ---------------- index normalization: tolerate int32 OR int64 delivery ----------------
// int64 little-endian with values < 6720 => odd 32-bit words of the first entries are 0.
// int32 => those words are random node indices (all-zero probability ~0).
__global__ void k_cvt(const int* __restrict__ ei, const int* __restrict__ conn) {
    bool is64 = true;
#pragma unroll
    for (int i = 0; i < 16; i++)
        if (ei[2 * i + 1] != 0) is64 = false;
    int t = blockIdx.x * blockDim.x + threadIdx.x;
    int stride = gridDim.x * blockDim.x;
    if (is64) {
        for (int i = t; i < NEDGE; i += stride) {
            g_src[i] = ei[2 * i];
            g_dst[i] = ei[2 * (NEDGE + i)];
        }
        for (int i = t; i < NN; i += stride) g_conn[i] = conn[2 * i];
    } else {
        for (int i = t; i < NEDGE; i += stride) {
            g_src[i] = ei[i];
            g_dst[i] = ei[NEDGE + i];
        }
        for (int i = t; i < NN; i += stride) g_conn[i] = conn[i];
    }
}

// ---------------- zero scratch that is accumulated into ----------------
__global__ void k_zero() {
    size_t i = (size_t)blockIdx.x * blockDim.x + threadIdx.x;
    size_t stride = (size_t)gridDim.x * blockDim.x;
    for (size_t j = i; j < (size_t)NN * C1; j += stride) g_att1[j] = 0.f;
    for (size_t j = i; j < (size_t)NN * H2; j += stride) g_att2[j] = 0.f;
    for (size_t j = i; j < (size_t)NN * 2; j += stride) g_dn1[j] = 0.f;
    for (size_t j = i; j < (size_t)NN; j += stride) g_dn2[j] = 0.f;
}

// ---------------- positional-embedding add ----------------
__global__ void k_pe(const float* __restrict__ x,
                     const float* __restrict__ npe, const float* __restrict__ lpe,
                     const float* __restrict__ gpe) {
    int node = blockIdx.x;
    int lobe = g_conn[node] - 1;            // 0..4
    int lung = (lobe <= 1) ? 0 : 1;         // conn<=2 -> 0 else 1
    const float4* xp = (const float4*)(x + (size_t)node * INDIM);
    const float4* np = (const float4*)(npe + (size_t)(node % NODESP) * INDIM);
    const float4* lp = (const float4*)(lpe + (size_t)lobe * INDIM);
    const float4* gp = (const float4*)(gpe + (size_t)lung * INDIM);
    float4* hp = (float4*)(g_h + (size_t)node * INDIM);
    for (int j = threadIdx.x; j < INDIM / 4; j += blockDim.x) {
        float4 a = xp[j], b = np[j], c = lp[j], d = gp[j];
        float4 o;
        o.x = a.x + b.x + c.x + d.x;
        o.y = a.y + b.y + c.y + d.y;
        o.z = a.z + b.z + c.z + d.z;
        o.w = a.w + b.w + c.w + d.w;
        hp[j] = o;
    }
}

// ---------------- 128x128x8 fp32 SGEMM, C = A@W + bias (opt relu) ----------------
__global__ __launch_bounds__(256) void sgemm(
    const float* __restrict__ A, const float* __restrict__ W,
    const float* __restrict__ bias, float* __restrict__ C,
    int M, int N, int K, int relu) {
    const int BM = 128, BN = 128, BK = 8;
    __shared__ float As[BK][132];
    __shared__ float Bs[BK][BN];
    int tid = threadIdx.x;
    int bx = blockIdx.x, by = blockIdx.y;
    int arow = tid >> 1;
    int acol = (tid & 1) << 2;
    int brow = tid >> 5;
    int bcol = (tid & 31) << 2;
    int ty = (tid >> 4) << 3;
    int tx = (tid & 15) << 3;

    float acc[8][8];
#pragma unroll
    for (int i = 0; i < 8; i++)
#pragma unroll
        for (int j = 0; j < 8; j++) acc[i][j] = 0.f;

    int grow = by * BM + arow;
    int gcolB = bx * BN + bcol;
    bool aok = grow < M;
    bool bok = gcolB < N;
    const float* Ap = A + (size_t)grow * K;

    for (int k0 = 0; k0 < K; k0 += BK) {
        float4 av = aok ? *(const float4*)(Ap + k0 + acol) : make_float4(0.f, 0.f, 0.f, 0.f);
        As[acol + 0][arow] = av.x;
        As[acol + 1][arow] = av.y;
        As[acol + 2][arow] = av.z;
        As[acol + 3][arow] = av.w;
        float4 bv = bok ? *(const float4*)(W + (size_t)(k0 + brow) * N + gcolB)
                        : make_float4(0.f, 0.f, 0.f, 0.f);
        *(float4*)&Bs[brow][bcol] = bv;
        __syncthreads();
#pragma unroll
        for (int kk = 0; kk < BK; kk++) {
            float ar[8], br[8];
            *(float4*)&ar[0] = *(const float4*)&As[kk][ty];
            *(float4*)&ar[4] = *(const float4*)&As[kk][ty + 4];
            *(float4*)&br[0] = *(const float4*)&Bs[kk][tx];
            *(float4*)&br[4] = *(const float4*)&Bs[kk][tx + 4];
#pragma unroll
            for (int i = 0; i < 8; i++)
#pragma unroll
                for (int j = 0; j < 8; j++) acc[i][j] = fmaf(ar[i], br[j], acc[i][j]);
        }
        __syncthreads();
    }

#pragma unroll
    for (int i = 0; i < 8; i++) {
        int r = by * BM + ty + i;
        if (r >= M) break;
#pragma unroll
        for (int j = 0; j < 8; j++) {
            int c = bx * BN + tx + j;
            if (c < N) {
                float v = acc[i][j] + bias[c];
                if (relu) v = fmaxf(v, 0.f);
                C[(size_t)r * N + c] = v;
            }
        }
    }
}

// ---------------- conv1 attention (heads=2, d=1024, scale 1/32) ----------------
__global__ void k_alpha1() {
    int e = blockIdx.x;
    int head = threadIdx.x >> 5;
    int lane = threadIdx.x & 31;
    int src = g_src[e];
    int dst = g_dst[e];
    const float* q = g_q1 + (size_t)dst * C1 + head * H1;
    const float* k = g_k1 + (size_t)src * C1 + head * H1;
    float s = 0.f;
    for (int j = lane; j < H1; j += 32) s = fmaf(q[j], k[j], s);
#pragma unroll
    for (int off = 16; off; off >>= 1) s += __shfl_xor_sync(0xffffffffu, s, off);
    if (lane == 0) {
        // softmax is shift-invariant; alpha is O(1) so exp() is safe without segment_max
        float ex = expf(s * (1.f / 32.f));
        g_al1[e * 2 + head] = ex;
        atomicAdd(&g_dn1[dst * 2 + head], ex);
    }
}

__global__ void k_scatter1() {
    int e = blockIdx.x;
    int head = threadIdx.x >> 5;
    int lane = threadIdx.x & 31;
    int src = g_src[e];
    int dst = g_dst[e];
    float a = g_al1[e * 2 + head] / (g_dn1[dst * 2 + head] + 1e-16f);
    const float* v = g_v1 + (size_t)src * C1 + head * H1;
    float* o = g_att1 + (size_t)dst * C1 + head * H1;
    for (int j = lane; j < H1; j += 32) atomicAdd(&o[j], a * v[j]);
}

__global__ void k_epi1() {
    size_t i = (size_t)blockIdx.x * blockDim.x + threadIdx.x;
    size_t stride = (size_t)gridDim.x * blockDim.x;
    for (size_t j = i; j < (size_t)NN * C1; j += stride)
        g_out1[j] = fmaxf(g_att1[j] + g_s1[j], 0.f);
}

// ---------------- conv2 attention (heads=1, d=64, scale 1/8) ----------------
__global__ void k_alpha2() {
    int e = blockIdx.x * 8 + (threadIdx.x >> 5);
    if (e >= NEDGE) return;
    int lane = threadIdx.x & 31;
    int src = g_src[e];
    int dst = g_dst[e];
    const float* q = g_q2 + (size_t)dst * H2;
    const float* k = g_k2 + (size_t)src * H2;
    float s = fmaf(q[lane], k[lane], 0.f) + q[lane + 32] * k[lane + 32];
#pragma unroll
    for (int off = 16; off; off >>= 1) s += __shfl_xor_sync(0xffffffffu, s, off);
    if (lane == 0) {
        float ex = expf(s * 0.125f);
        g_al2[e] = ex;
        atomicAdd(&g_dn2[dst], ex);
    }
}

__global__ void k_scatter2() {
    int e = blockIdx.x * 8 + (threadIdx.x >> 5);
    if (e >= NEDGE) return;
    int lane = threadIdx.x & 31;
    int src = g_src[e];
    int dst = g_dst[e];
    float a = g_al2[e] / (g_dn2[dst] + 1e-16f);
    const float* v = g_v2 + (size_t)src * H2;
    float* o = g_att2 + (size_t)dst * H2;
    atomicAdd(&o[lane], a * v[lane]);
    atomicAdd(&o[lane + 32], a * v[lane + 32]);
}

__global__ void k_epi2() {
    size_t i = (size_t)blockIdx.x * blockDim.x + threadIdx.x;
    size_t stride = (size_t)gridDim.x * blockDim.x;
    for (size_t j = i; j < (size_t)NN * H2; j += stride)
        g_out2[j] = fmaxf(g_att2[j] + g_s2[j], 0.f);
}

// ---------------- small FC ----------------
__global__ void fc(const float* __restrict__ A, const float* __restrict__ W,
                   const float* __restrict__ b, float* __restrict__ C,
                   int N, int K, int relu) {
    int m = blockIdx.x;
    int n = threadIdx.x;
    if (n >= N) return;
    const float* a = A + (size_t)m * K;
    float s0 = 0.f, s1 = 0.f, s2 = 0.f, s3 = 0.f;
    int k = 0;
    for (; k + 4 <= K; k += 4) {
        s0 = fmaf(a[k + 0], W[(size_t)(k + 0) * N + n], s0);
        s1 = fmaf(a[k + 1], W[(size_t)(k + 1) * N + n], s1);
        s2 = fmaf(a[k + 2], W[(size_t)(k + 2) * N + n], s2);
        s3 = fmaf(a[k + 3], W[(size_t)(k + 3) * N + n], s3);
    }
    for (; k < K; k++) s0 = fmaf(a[k], W[(size_t)k * N + n], s0);
    float s = (s0 + s1) + (s2 + s3) + b[n];
    if (relu) s = fmaxf(s, 0.f);
    C[(size_t)m * N + n] = s;
}

// ---------------- launch ----------------
extern "C" void kernel_launch(void* const* d_in, const int* in_sizes, int n_in,
                              void* d_out, int out_size) {
    const float* x = (const float*)d_in[0];
    const int* ei = (const int*)d_in[1];
    const int* conn = (const int*)d_in[2];
    const float* npe = (const float*)d_in[3];
    const float* lpe = (const float*)d_in[4];
    const float* gpe = (const float*)d_in[5];
    const float* Wq1 = (const float*)d_in[6];  const float* bq1 = (const float*)d_in[7];
    const float* Wk1 = (const float*)d_in[8];  const float* bk1 = (const float*)d_in[9];
    const float* Wv1 = (const float*)d_in[10]; const float* bv1 = (const float*)d_in[11];
    const float* Ws1 = (const float*)d_in[12]; const float* bs1 = (const float*)d_in[13];
    const float* Wq2 = (const float*)d_in[14]; const float* bq2 = (const float*)d_in[15];
    const float* Wk2 = (const float*)d_in[16]; const float* bk2 = (const float*)d_in[17];
    const float* Wv2 = (const float*)d_in[18]; const float* bv2 = (const float*)d_in[19];
    const float* Ws2 = (const float*)d_in[20]; const float* bs2 = (const float*)d_in[21];
    const float* Wf1 = (const float*)d_in[22]; const float* bf1 = (const float*)d_in[23];
    const float* Wf2 = (const float*)d_in[24]; const float* bf2 = (const float*)d_in[25];
    const float* Wf3 = (const float*)d_in[26]; const float* bf3 = (const float*)d_in[27];
    const float* Wf4 = (const float*)d_in[28]; const float* bf4 = (const float*)d_in[29];

    float *h_, *q1, *k1, *v1, *s1, *out1, *q2, *k2, *v2, *s2, *out2, *f1, *f2, *f3;
    cudaGetSymbolAddress((void**)&h_, g_h);
    cudaGetSymbolAddress((void**)&q1, g_q1);
    cudaGetSymbolAddress((void**)&k1, g_k1);
    cudaGetSymbolAddress((void**)&v1, g_v1);
    cudaGetSymbolAddress((void**)&s1, g_s1);
    cudaGetSymbolAddress((void**)&out1, g_out1);
    cudaGetSymbolAddress((void**)&q2, g_q2);
    cudaGetSymbolAddress((void**)&k2, g_k2);
    cudaGetSymbolAddress((void**)&v2, g_v2);
    cudaGetSymbolAddress((void**)&s2, g_s2);
    cudaGetSymbolAddress((void**)&out2, g_out2);
    cudaGetSymbolAddress((void**)&f1, g_f1);
    cudaGetSymbolAddress((void**)&f2, g_f2);
    cudaGetSymbolAddress((void**)&f3, g_f3);

    k_cvt<<<256, 256>>>(ei, conn);
    k_zero<<<1184, 256>>>();
    k_pe<<<NN, 512>>>(x, npe, lpe, gpe);

    dim3 g1(C1 / 128, (NN + 127) / 128);  // (16, 53)
    sgemm<<<g1, 256>>>(h_, Wq1, bq1, q1, NN, C1, INDIM, 0);
    sgemm<<<g1, 256>>>(h_, Wk1, bk1, k1, NN, C1, INDIM, 0);
    sgemm<<<g1, 256>>>(h_, Wv1, bv1, v1, NN, C1, INDIM, 0);
    sgemm<<<g1, 256>>>(h_, Ws1, bs1, s1, NN, C1, INDIM, 0);

    k_alpha1<<<NEDGE, 64>>>();
    k_scatter1<<<NEDGE, 64>>>();
    k_epi1<<<2048, 256>>>();

    dim3 g2(1, (NN + 127) / 128);         // (1, 53)
    sgemm<<<g2, 256>>>(out1, Wq2, bq2, q2, NN, H2, C1, 0);
    sgemm<<<g2, 256>>>(out1, Wk2, bk2, k2, NN, H2, C1, 0);
    sgemm<<<g2, 256>>>(out1, Wv2, bv2, v2, NN, H2, C1, 0);
    sgemm<<<g2, 256>>>(out1, Ws2, bs2, s2, NN, H2, C1, 0);

    k_alpha2<<<NEDGE / 8, 256>>>();
    k_scatter2<<<NEDGE / 8, 256>>>();
    k_epi2<<<512, 256>>>();

    fc<<<NGRAPH, 256>>>(out2, Wf1, bf1, f1, 256, FCK, 1);
    fc<<<NGRAPH, 128>>>(f1, Wf2, bf2, f2, 128, 256, 1);
    fc<<<NGRAPH, 64>>>(f2, Wf3, bf3, f3, 64, 128, 1);
    fc<<<NGRAPH, 32>>>(f3, Wf4, bf4, (float*)d_out, OUTD, 64, 0);
}

// round 8
// speedup vs baseline: 3.9960x; 3.9960x over previous
#include <cuda_runtime.h>
#include <cuda_bf16.h>
#include <cstdint>

#define NGRAPH 16
#define NODESP 420
#define NN     6720
#define NP     6784    // padded to 53*128
#define NEDGE  53760
#define INDIM  2048
#define C1     2048
#define H1     1024
#define H2     64
#define OUTD   18
#define FCK    26880
#define NW1    8192    // 4 fused conv1 weight mats
#define NW2    256     // 4 fused conv2 weight mats
#define KTOT   2048

// ======================= device scratch =======================
__device__ float g_c1[(size_t)NP * NW1];            // fused q|k|v|s conv1 out
__device__ float g_att1[(size_t)NP * C1];
__device__ float g_al1[NEDGE * 2];
__device__ float g_dn1[NN * 2];
__device__ float g_c2[(size_t)NP * NW2];            // fused q|k|v|s conv2 out
__device__ float g_att2[(size_t)NP * H2];
__device__ float g_out2[(size_t)NN * H2];
__device__ float g_al2[NEDGE];
__device__ float g_dn2[NN];
__device__ float g_f1[NGRAPH * 256];
__device__ float g_f2[NGRAPH * 128];
__device__ float g_f3[NGRAPH * 64];
__device__ int   g_src[NEDGE];
__device__ int   g_dst[NEDGE];
__device__ int   g_conn[NN];
__device__ __nv_bfloat16 g_ah[(size_t)NP * INDIM];   // A1 split
__device__ __nv_bfloat16 g_al_[(size_t)NP * INDIM];
__device__ __nv_bfloat16 g_a2h[(size_t)NP * C1];     // A2 split
__device__ __nv_bfloat16 g_a2l[(size_t)NP * C1];
__device__ __nv_bfloat16 g_w1th[(size_t)NW1 * INDIM]; // W1^T split [n][k]
__device__ __nv_bfloat16 g_w1tl[(size_t)NW1 * INDIM];
__device__ __nv_bfloat16 g_w2th[(size_t)NW2 * C1];
__device__ __nv_bfloat16 g_w2tl[(size_t)NW2 * C1];
__device__ float g_bc1[NW1];
__device__ float g_bc2[NW2];

// ======================= sm_80-baseline PTX wrappers =======================
__device__ __forceinline__ uint32_t smem_u32(const void* p) {
    uint32_t a;
    asm("{ .reg .u64 t; cvta.to.shared.u64 t, %1; cvt.u32.u64 %0, t; }" : "=r"(a) : "l"(p));
    return a;
}
__device__ __forceinline__ void cpa16(uint32_t s, const void* g) {
    asm volatile("cp.async.cg.shared.global [%0], [%1], 16;" :: "r"(s), "l"(g));
}
__device__ __forceinline__ void cpa_commit() {
    asm volatile("cp.async.commit_group;" ::: "memory");
}
__device__ __forceinline__ void cpa_wait2() {
    asm volatile("cp.async.wait_group 2;" ::: "memory");
}
__device__ __forceinline__ void ldsm4(uint32_t* r, uint32_t addr) {
    asm volatile("ldmatrix.sync.aligned.m8n8.x4.shared.b16 {%0,%1,%2,%3}, [%4];"
        : "=r"(r[0]), "=r"(r[1]), "=r"(r[2]), "=r"(r[3]) : "r"(addr));
}
__device__ __forceinline__ void mma16816(float* d, const uint32_t* a, const uint32_t* b) {
    asm volatile("mma.sync.aligned.m16n8k16.row.col.f32.bf16.bf16.f32 "
        "{%0,%1,%2,%3}, {%4,%5,%6,%7}, {%8,%9}, {%0,%1,%2,%3};"
        : "+f"(d[0]), "+f"(d[1]), "+f"(d[2]), "+f"(d[3])
        : "r"(a[0]), "r"(a[1]), "r"(a[2]), "r"(a[3]), "r"(b[0]), "r"(b[1]));
}

// ======================= index normalization =======================
__global__ void k_cvt(const int* __restrict__ ei, const int* __restrict__ conn) {
    bool is64 = true;
#pragma unroll
    for (int i = 0; i < 16; i++)
        if (ei[2 * i + 1] != 0) is64 = false;
    int t = blockIdx.x * blockDim.x + threadIdx.x;
    int stride = gridDim.x * blockDim.x;
    if (is64) {
        for (int i = t; i < NEDGE; i += stride) { g_src[i] = ei[2 * i]; g_dst[i] = ei[2 * (NEDGE + i)]; }
        for (int i = t; i < NN; i += stride) g_conn[i] = conn[2 * i];
    } else {
        for (int i = t; i < NEDGE; i += stride) { g_src[i] = ei[i]; g_dst[i] = ei[NEDGE + i]; }
        for (int i = t; i < NN; i += stride) g_conn[i] = conn[i];
    }
}

__global__ void k_zero() {
    size_t i = (size_t)blockIdx.x * blockDim.x + threadIdx.x;
    size_t stride = (size_t)gridDim.x * blockDim.x;
    for (size_t j = i; j < (size_t)NP * C1; j += stride) g_att1[j] = 0.f;
    for (size_t j = i; j < (size_t)NP * H2; j += stride) g_att2[j] = 0.f;
    for (size_t j = i; j < (size_t)NN * 2; j += stride) g_dn1[j] = 0.f;
    for (size_t j = i; j < (size_t)NN; j += stride) g_dn2[j] = 0.f;
    for (size_t j = i; j < (size_t)NGRAPH * 256; j += stride) g_f1[j] = 0.f;
}

// ======================= PE add + bf16 split of A1 =======================
__global__ void k_pe(const float* __restrict__ x, const float* __restrict__ npe,
                     const float* __restrict__ lpe, const float* __restrict__ gpe) {
    int node = blockIdx.x;
    __nv_bfloat16* ah = g_ah + (size_t)node * INDIM;
    __nv_bfloat16* al = g_al_ + (size_t)node * INDIM;
    if (node >= NN) {
        for (int j = threadIdx.x; j < INDIM / 2; j += blockDim.x) {
            ((uint32_t*)ah)[j] = 0u; ((uint32_t*)al)[j] = 0u;
        }
        return;
    }
    int lobe = g_conn[node] - 1;
    int lung = (lobe <= 1) ? 0 : 1;
    const float4* xp = (const float4*)(x + (size_t)node * INDIM);
    const float4* np = (const float4*)(npe + (size_t)(node % NODESP) * INDIM);
    const float4* lp = (const float4*)(lpe + (size_t)lobe * INDIM);
    const float4* gp = (const float4*)(gpe + (size_t)lung * INDIM);
    for (int j = threadIdx.x; j < INDIM / 4; j += blockDim.x) {
        float4 a = xp[j], b = np[j], c = lp[j], d = gp[j];
        float v[4] = { a.x + b.x + c.x + d.x, a.y + b.y + c.y + d.y,
                       a.z + b.z + c.z + d.z, a.w + b.w + c.w + d.w };
        __nv_bfloat16 h[4], l[4];
#pragma unroll
        for (int q = 0; q < 4; q++) {
            h[q] = __float2bfloat16(v[q]);
            l[q] = __float2bfloat16(v[q] - __bfloat162float(h[q]));
        }
        ((__nv_bfloat162*)ah)[2 * j]     = __halves2bfloat162(h[0], h[1]);
        ((__nv_bfloat162*)ah)[2 * j + 1] = __halves2bfloat162(h[2], h[3]);
        ((__nv_bfloat162*)al)[2 * j]     = __halves2bfloat162(l[0], l[1]);
        ((__nv_bfloat162*)al)[2 * j + 1] = __halves2bfloat162(l[2], l[3]);
    }
}

// ======================= weight transpose + split =======================
// W [K][Nw] fp32 -> Th/Tl [noff+n][k] bf16 (row stride = K)
__global__ void k_wsplit(const float* __restrict__ W, __nv_bfloat16* __restrict__ Th,
                         __nv_bfloat16* __restrict__ Tl, int Nw, int K, int noff) {
    __shared__ float tile[32][33];
    int n0 = blockIdx.x * 32, k0 = blockIdx.y * 32;
    int tx = threadIdx.x, ty = threadIdx.y;  // 32 x 8
#pragma unroll
    for (int r = 0; r < 4; r++)
        tile[ty + r * 8][tx] = W[(size_t)(k0 + ty + r * 8) * Nw + n0 + tx];
    __syncthreads();
#pragma unroll
    for (int r = 0; r < 4; r++) {
        int n = n0 + ty + r * 8;
        float v = tile[tx][ty + r * 8];
        __nv_bfloat16 h = __float2bfloat16(v);
        Th[(size_t)(noff + n) * K + k0 + tx] = h;
        Tl[(size_t)(noff + n) * K + k0 + tx] = __float2bfloat16(v - __bfloat162float(h));
    }
}

__global__ void k_bias(const float* b0, const float* b1, const float* b2, const float* b3,
                       const float* c0, const float* c1_, const float* c2, const float* c3) {
    int t = blockIdx.x * blockDim.x + threadIdx.x;
    if (t < NW1) {
        int w = t >> 11, j = t & 2047;
        g_bc1[t] = (w == 0 ? b0 : w == 1 ? b1 : w == 2 ? b2 : b3)[j];
    }
    if (t < NW2) {
        int w = t >> 6, j = t & 63;
        g_bc2[t] = (w == 0 ? c0 : w == 1 ? c1_ : w == 2 ? c2 : c3)[j];
    }
}

// ======================= mma.sync split-bf16 GEMM =======================
// C[m][n] = sum_k (Ah+Al)[m][k]*(Bh+Bl)[n][k] + bias[n], K=2048.
// BM=128, BN=128, BK=32. 8 warps in 2(M)x4(N); warp tile 64x32.
// smem stage: A 128 rows x 128B = [Ah 64B | Al 64B], swizzled; B same.
#define ASTAGE 16384
#define STAGE  32768
#define GSMEM  (3 * STAGE)
#define NCHUNK (KTOT / 32)

__device__ __forceinline__ uint32_t swz(int row, int ch) {
    return (uint32_t)(row * 128 + ((ch ^ (row & 7)) << 4));
}

__device__ __forceinline__ void load_stage(uint32_t sbase, int tid, int s, int c,
        const __nv_bfloat16* __restrict__ Ah, const __nv_bfloat16* __restrict__ Al,
        const __nv_bfloat16* __restrict__ Bh, const __nv_bfloat16* __restrict__ Bl,
        int m0, int n0) {
    uint32_t sa = sbase + s * STAGE;
    uint32_t sb = sa + ASTAGE;
    int k0 = c * 32;
#pragma unroll
    for (int i = 0; i < 4; i++) {
        int idx = tid + i * 256;          // 0..1023
        int r = idx >> 3, ch = idx & 7;
        const __nv_bfloat16* g = (ch < 4)
            ? (Ah + (size_t)(m0 + r) * KTOT + k0 + ch * 8)
            : (Al + (size_t)(m0 + r) * KTOT + k0 + (ch - 4) * 8);
        cpa16(sa + swz(r, ch), g);
    }
#pragma unroll
    for (int i = 0; i < 4; i++) {
        int idx = tid + i * 256;
        int r = idx >> 3, ch = idx & 7;
        const __nv_bfloat16* g = (ch < 4)
            ? (Bh + (size_t)(n0 + r) * KTOT + k0 + ch * 8)
            : (Bl + (size_t)(n0 + r) * KTOT + k0 + (ch - 4) * 8);
        cpa16(sb + swz(r, ch), g);
    }
    cpa_commit();
}

__global__ void __launch_bounds__(256, 1) mm_gemm(
        const __nv_bfloat16* __restrict__ Ah, const __nv_bfloat16* __restrict__ Al,
        const __nv_bfloat16* __restrict__ Bh, const __nv_bfloat16* __restrict__ Bl,
        const float* __restrict__ bias, float* __restrict__ C, int ldc) {
    extern __shared__ char smem[];
    uint32_t sbase = smem_u32(smem);
    int tid = threadIdx.x, lane = tid & 31, wid = tid >> 5;
    int wm = wid >> 2, wn = wid & 3;       // 2 x 4
    int m0 = blockIdx.y * 128, n0 = blockIdx.x * 128;

    float acc[4][4][4];
#pragma unroll
    for (int i = 0; i < 4; i++)
#pragma unroll
        for (int j = 0; j < 4; j++)
#pragma unroll
            for (int q = 0; q < 4; q++) acc[i][j][q] = 0.f;

    load_stage(sbase, tid, 0, 0, Ah, Al, Bh, Bl, m0, n0);
    load_stage(sbase, tid, 1, 1, Ah, Al, Bh, Bl, m0, n0);
    load_stage(sbase, tid, 2, 2, Ah, Al, Bh, Bl, m0, n0);

    // precomputed ldmatrix lane geometry
    int a_row_l = (lane & 15);             // + wm*64 + mt*16
    int a_chl   = (lane >> 4);             // + sel*4 + ks*2
    int b_row_l = (lane & 7) + ((lane >> 4) << 3);  // + wn*32 + np*16
    int b_chl   = ((lane >> 3) & 1);       // + sel*4 + ks*2

    for (int c = 0; c < NCHUNK; c++) {
        cpa_wait2();
        __syncthreads();
        uint32_t sa = sbase + (c % 3) * STAGE;
        uint32_t sb = sa + ASTAGE;
#pragma unroll
        for (int ks = 0; ks < 2; ks++) {
            uint32_t a_hi[4][4], a_lo[4][4], b_hi[2][4], b_lo[2][4];
#pragma unroll
            for (int mt = 0; mt < 4; mt++) {
                int row = wm * 64 + mt * 16 + a_row_l;
                ldsm4(a_hi[mt], sa + swz(row, 0 + ks * 2 + a_chl));
                ldsm4(a_lo[mt], sa + swz(row, 4 + ks * 2 + a_chl));
            }
#pragma unroll
            for (int np = 0; np < 2; np++) {
                int row = wn * 32 + np * 16 + b_row_l;
                ldsm4(b_hi[np], sb + swz(row, 0 + ks * 2 + b_chl));
                ldsm4(b_lo[np], sb + swz(row, 4 + ks * 2 + b_chl));
            }
#pragma unroll
            for (int mt = 0; mt < 4; mt++)
#pragma unroll
                for (int nt = 0; nt < 4; nt++) {
                    const uint32_t* bh = &b_hi[nt >> 1][(nt & 1) * 2];
                    const uint32_t* bl = &b_lo[nt >> 1][(nt & 1) * 2];
                    mma16816(acc[mt][nt], a_hi[mt], bh);
                    mma16816(acc[mt][nt], a_hi[mt], bl);
                    mma16816(acc[mt][nt], a_lo[mt], bh);
                }
        }
        __syncthreads();
        if (c + 3 < NCHUNK)
            load_stage(sbase, tid, c % 3, c + 3, Ah, Al, Bh, Bl, m0, n0);
        else
            cpa_commit();
    }

#pragma unroll
    for (int mt = 0; mt < 4; mt++) {
        int row = m0 + wm * 64 + mt * 16 + (lane >> 2);
#pragma unroll
        for (int nt = 0; nt < 4; nt++) {
            int col = n0 + wn * 32 + nt * 8 + (lane & 3) * 2;
            float b0 = bias[col], b1 = bias[col + 1];
            float* p0 = C + (size_t)row * ldc + col;
            p0[0] = acc[mt][nt][0] + b0;
            p0[1] = acc[mt][nt][1] + b1;
            float* p1 = p0 + 8 * ldc;
            p1[0] = acc[mt][nt][2] + b0;
            p1[1] = acc[mt][nt][3] + b1;
        }
    }
}

// ======================= conv1 attention =======================
// g_c1 per-node (stride 8192): q[0:2048] k[2048:4096] v[4096:6144] s[6144:8192]
__global__ void k_alpha1() {
    int e = blockIdx.x;
    int head = threadIdx.x >> 5;
    int lane = threadIdx.x & 31;
    int src = g_src[e], dst = g_dst[e];
    const float* q = g_c1 + (size_t)dst * NW1 + head * H1;
    const float* k = g_c1 + (size_t)src * NW1 + 2048 + head * H1;
    float s = 0.f;
    for (int j = lane; j < H1; j += 32) s = fmaf(q[j], k[j], s);
#pragma unroll
    for (int off = 16; off; off >>= 1) s += __shfl_xor_sync(0xffffffffu, s, off);
    if (lane == 0) {
        float ex = expf(s * (1.f / 32.f));
        g_al1[e * 2 + head] = ex;
        atomicAdd(&g_dn1[dst * 2 + head], ex);
    }
}

__global__ void k_scatter1() {
    int e = blockIdx.x;
    int head = threadIdx.x >> 5;
    int lane = threadIdx.x & 31;
    int src = g_src[e], dst = g_dst[e];
    float a = g_al1[e * 2 + head] / (g_dn1[dst * 2 + head] + 1e-16f);
    const float* v = g_c1 + (size_t)src * NW1 + 4096 + head * H1;
    float* o = g_att1 + (size_t)dst * C1 + head * H1;
    for (int j = lane; j < H1; j += 32) atomicAdd(&o[j], a * v[j]);
}

// out1 = relu(att1 + skip) -> bf16 split A2 (pad rows -> 0)
__global__ void k_epi1() {
    size_t i = (size_t)blockIdx.x * blockDim.x + threadIdx.x;
    size_t stride = (size_t)gridDim.x * blockDim.x;
    for (size_t j = i; j < (size_t)NP * C1; j += stride) {
        size_t node = j >> 11;
        int col = (int)(j & 2047);
        float v = 0.f;
        if (node < NN)
            v = fmaxf(g_att1[j] + g_c1[node * NW1 + 6144 + col], 0.f);
        __nv_bfloat16 h = __float2bfloat16(v);
        g_a2h[j] = h;
        g_a2l[j] = __float2bfloat16(v - __bfloat162float(h));
    }
}

// ======================= conv2 attention =======================
// g_c2 per-node (stride 256): q[0:64] k[64:128] v[128:192] s[192:256]
__global__ void k_alpha2() {
    int e = blockIdx.x * 8 + (threadIdx.x >> 5);
    if (e >= NEDGE) return;
    int lane = threadIdx.x & 31;
    int src = g_src[e], dst = g_dst[e];
    const float* q = g_c2 + (size_t)dst * NW2;
    const float* k = g_c2 + (size_t)src * NW2 + 64;
    float s = q[lane] * k[lane] + q[lane + 32] * k[lane + 32];
#pragma unroll
    for (int off = 16; off; off >>= 1) s += __shfl_xor_sync(0xffffffffu, s, off);
    if (lane == 0) {
        float ex = expf(s * 0.125f);
        g_al2[e] = ex;
        atomicAdd(&g_dn2[dst], ex);
    }
}

__global__ void k_scatter2() {
    int e = blockIdx.x * 8 + (threadIdx.x >> 5);
    if (e >= NEDGE) return;
    int lane = threadIdx.x & 31;
    int src = g_src[e], dst = g_dst[e];
    float a = g_al2[e] / (g_dn2[dst] + 1e-16f);
    const float* v = g_c2 + (size_t)src * NW2 + 128;
    float* o = g_att2 + (size_t)dst * H2;
    atomicAdd(&o[lane], a * v[lane]);
    atomicAdd(&o[lane + 32], a * v[lane + 32]);
}

__global__ void k_epi2() {
    size_t i = (size_t)blockIdx.x * blockDim.x + threadIdx.x;
    size_t stride = (size_t)gridDim.x * blockDim.x;
    for (size_t j = i; j < (size_t)NN * H2; j += stride) {
        size_t node = j >> 6;
        int col = (int)(j & 63);
        g_out2[j] = fmaxf(g_att2[j] + g_c2[node * NW2 + 192 + col], 0.f);
    }
}

// ======================= FC head =======================
__global__ void fc1s(const float* __restrict__ W, const float* __restrict__ b) {
    int g = blockIdx.x, ks = blockIdx.y, n = threadIdx.x;
    const float* a = g_out2 + (size_t)g * FCK + ks * 1920;
    const float* w = W + (size_t)ks * 1920 * 256 + n;
    float s0 = (ks == 0) ? b[n] : 0.f, s1 = 0.f, s2 = 0.f, s3 = 0.f;
    for (int k = 0; k < 1920; k += 4) {
        s0 = fmaf(a[k + 0], w[(size_t)(k + 0) * 256], s0);
        s1 = fmaf(a[k + 1], w[(size_t)(k + 1) * 256], s1);
        s2 = fmaf(a[k + 2], w[(size_t)(k + 2) * 256], s2);
        s3 = fmaf(a[k + 3], w[(size_t)(k + 3) * 256], s3);
    }
    atomicAdd(&g_f1[g * 256 + n], (s0 + s1) + (s2 + s3));
}

__global__ void fc(const float* __restrict__ A, const float* __restrict__ W,
                   const float* __restrict__ b, float* __restrict__ C,
                   int N, int K, int relu_out, int relu_in) {
    int m = blockIdx.x, n = threadIdx.x;
    if (n >= N) return;
    const float* a = A + (size_t)m * K;
    float s = b[n];
    for (int k = 0; k < K; k++) {
        float av = a[k];
        if (relu_in) av = fmaxf(av, 0.f);
        s = fmaf(av, W[(size_t)k * N + n], s);
    }
    if (relu_out) s = fmaxf(s, 0.f);
    C[(size_t)m * N + n] = s;
}

// ======================= launch =======================
extern "C" void kernel_launch(void* const* d_in, const int* in_sizes, int n_in,
                              void* d_out, int out_size) {
    const float* x = (const float*)d_in[0];
    const int* ei = (const int*)d_in[1];
    const int* conn = (const int*)d_in[2];
    const float* npe = (const float*)d_in[3];
    const float* lpe = (const float*)d_in[4];
    const float* gpe = (const float*)d_in[5];
    const float* Wq1 = (const float*)d_in[6];  const float* bq1 = (const float*)d_in[7];
    const float* Wk1 = (const float*)d_in[8];  const float* bk1 = (const float*)d_in[9];
    const float* Wv1 = (const float*)d_in[10]; const float* bv1 = (const float*)d_in[11];
    const float* Ws1 = (const float*)d_in[12]; const float* bs1 = (const float*)d_in[13];
    const float* Wq2 = (const float*)d_in[14]; const float* bq2 = (const float*)d_in[15];
    const float* Wk2 = (const float*)d_in[16]; const float* bk2 = (const float*)d_in[17];
    const float* Wv2 = (const float*)d_in[18]; const float* bv2 = (const float*)d_in[19];
    const float* Ws2 = (const float*)d_in[20]; const float* bs2 = (const float*)d_in[21];
    const float* Wf1 = (const float*)d_in[22]; const float* bf1 = (const float*)d_in[23];
    const float* Wf2 = (const float*)d_in[24]; const float* bf2 = (const float*)d_in[25];
    const float* Wf3 = (const float*)d_in[26]; const float* bf3 = (const float*)d_in[27];
    const float* Wf4 = (const float*)d_in[28]; const float* bf4 = (const float*)d_in[29];

    cudaFuncSetAttribute(mm_gemm, cudaFuncAttributeMaxDynamicSharedMemorySize, GSMEM);

    float *c1p, *c2p, *f1p, *f2p, *f3p, *bc1p, *bc2p;
    __nv_bfloat16 *ahp, *alp, *a2hp, *a2lp, *w1hp, *w1lp, *w2hp, *w2lp;
    cudaGetSymbolAddress((void**)&c1p, g_c1);
    cudaGetSymbolAddress((void**)&c2p, g_c2);
    cudaGetSymbolAddress((void**)&f1p, g_f1);
    cudaGetSymbolAddress((void**)&f2p, g_f2);
    cudaGetSymbolAddress((void**)&f3p, g_f3);
    cudaGetSymbolAddress((void**)&bc1p, g_bc1);
    cudaGetSymbolAddress((void**)&bc2p, g_bc2);
    cudaGetSymbolAddress((void**)&ahp, g_ah);
    cudaGetSymbolAddress((void**)&alp, g_al_);
    cudaGetSymbolAddress((void**)&a2hp, g_a2h);
    cudaGetSymbolAddress((void**)&a2lp, g_a2l);
    cudaGetSymbolAddress((void**)&w1hp, g_w1th);
    cudaGetSymbolAddress((void**)&w1lp, g_w1tl);
    cudaGetSymbolAddress((void**)&w2hp, g_w2th);
    cudaGetSymbolAddress((void**)&w2lp, g_w2tl);

    k_cvt<<<256, 256>>>(ei, conn);
    k_zero<<<1184, 256>>>();
    k_pe<<<NP, 256>>>(x, npe, lpe, gpe);

    dim3 tb(32, 8);
    dim3 tg1(C1 / 32, INDIM / 32);
    k_wsplit<<<tg1, tb>>>(Wq1, w1hp, w1lp, C1, INDIM, 0);
    k_wsplit<<<tg1, tb>>>(Wk1, w1hp, w1lp, C1, INDIM, 2048);
    k_wsplit<<<tg1, tb>>>(Wv1, w1hp, w1lp, C1, INDIM, 4096);
    k_wsplit<<<tg1, tb>>>(Ws1, w1hp, w1lp, C1, INDIM, 6144);
    dim3 tg2(H2 / 32, C1 / 32);
    k_wsplit<<<tg2, tb>>>(Wq2, w2hp, w2lp, H2, C1, 0);
    k_wsplit<<<tg2, tb>>>(Wk2, w2hp, w2lp, H2, C1, 64);
    k_wsplit<<<tg2, tb>>>(Wv2, w2hp, w2lp, H2, C1, 128);
    k_wsplit<<<tg2, tb>>>(Ws2, w2hp, w2lp, H2, C1, 192);
    k_bias<<<(NW1 + 255) / 256, 256>>>(bq1, bk1, bv1, bs1, bq2, bk2, bv2, bs2);

    // conv1: fused 4-weight GEMM  [NP,2048] x [2048,8192]
    mm_gemm<<<dim3(NW1 / 128, NP / 128), 256, GSMEM>>>(ahp, alp, w1hp, w1lp, bc1p, c1p, NW1);

    k_alpha1<<<NEDGE, 64>>>();
    k_scatter1<<<NEDGE, 64>>>();
    k_epi1<<<2048, 256>>>();

    // conv2: fused 4-weight GEMM  [NP,2048] x [2048,256]
    mm_gemm<<<dim3(NW2 / 128, NP / 128), 256, GSMEM>>>(a2hp, a2lp, w2hp, w2lp, bc2p, c2p, NW2);

    k_alpha2<<<NEDGE / 8, 256>>>();
    k_scatter2<<<NEDGE / 8, 256>>>();
    k_epi2<<<512, 256>>>();

    fc1s<<<dim3(NGRAPH, 14), 256>>>(Wf1, bf1);
    fc<<<NGRAPH, 128>>>(f1p, Wf2, bf2, f2p, 128, 256, 1, 1);
    fc<<<NGRAPH, 64>>>(f2p, Wf3, bf3, f3p, 64, 128, 1, 0);
    fc<<<NGRAPH, 32>>>(f3p, Wf4, bf4, (float*)d_out, OUTD, 64, 0, 0);
}

// round 10
// speedup vs baseline: 4.2969x; 1.0753x over previous
#include <cuda_runtime.h>
#include <cuda_bf16.h>
#include <cstdint>

#define NGRAPH 16
#define NODESP 420
#define NN     6720
#define NP     6784    // padded to 53*128
#define NEDGE  53760
#define INDIM  2048
#define C1     2048
#define H1     1024
#define H2     64
#define OUTD   18
#define FCK    26880
#define NW1    8192    // 4 fused conv1 weight mats
#define NW2    256     // 4 fused conv2 weight mats
#define KTOT   2048

// ======================= device scratch =======================
__device__ float g_c1[(size_t)NP * NW1];            // fused q|k|v|s conv1 out
__device__ float g_al1[NEDGE * 2];                  // per-edge exp (spill)
__device__ float g_c2[(size_t)NP * NW2];            // fused q|k|v|s conv2 out
__device__ float g_out2[(size_t)NN * H2];
__device__ float g_al2[NEDGE];
__device__ float g_f1[NGRAPH * 256];
__device__ float g_f2[NGRAPH * 128];
__device__ float g_f3[NGRAPH * 64];
__device__ int   g_src[NEDGE];
__device__ int   g_dst[NEDGE];
__device__ int   g_conn[NN];
__device__ int   g_cnt[NN];
__device__ int   g_ofs[NN + 1];
__device__ int   g_wofs[NN];
__device__ int   g_eidx[NEDGE];
__device__ __nv_bfloat16 g_ah[(size_t)NP * INDIM];   // A1 split
__device__ __nv_bfloat16 g_al_[(size_t)NP * INDIM];
__device__ __nv_bfloat16 g_a2h[(size_t)NP * C1];     // A2 split
__device__ __nv_bfloat16 g_a2l[(size_t)NP * C1];
__device__ __nv_bfloat16 g_w1th[(size_t)NW1 * INDIM]; // W1^T split [n][k]
__device__ __nv_bfloat16 g_w1tl[(size_t)NW1 * INDIM];
__device__ __nv_bfloat16 g_w2th[(size_t)NW2 * C1];
__device__ __nv_bfloat16 g_w2tl[(size_t)NW2 * C1];
__device__ float g_bc1[NW1];
__device__ float g_bc2[NW2];

// ======================= sm_80-baseline PTX wrappers =======================
__device__ __forceinline__ uint32_t smem_u32(const void* p) {
    uint32_t a;
    asm("{ .reg .u64 t; cvta.to.shared.u64 t, %1; cvt.u32.u64 %0, t; }" : "=r"(a) : "l"(p));
    return a;
}
__device__ __forceinline__ void cpa16(uint32_t s, const void* g) {
    asm volatile("cp.async.cg.shared.global [%0], [%1], 16;" :: "r"(s), "l"(g));
}
__device__ __forceinline__ void cpa_commit() {
    asm volatile("cp.async.commit_group;" ::: "memory");
}
__device__ __forceinline__ void cpa_wait2() {
    asm volatile("cp.async.wait_group 2;" ::: "memory");
}
__device__ __forceinline__ void ldsm4(uint32_t* r, uint32_t addr) {
    asm volatile("ldmatrix.sync.aligned.m8n8.x4.shared.b16 {%0,%1,%2,%3}, [%4];"
        : "=r"(r[0]), "=r"(r[1]), "=r"(r[2]), "=r"(r[3]) : "r"(addr));
}
__device__ __forceinline__ void mma16816(float* d, const uint32_t* a, const uint32_t* b) {
    asm volatile("mma.sync.aligned.m16n8k16.row.col.f32.bf16.bf16.f32 "
        "{%0,%1,%2,%3}, {%4,%5,%6,%7}, {%8,%9}, {%0,%1,%2,%3};"
        : "+f"(d[0]), "+f"(d[1]), "+f"(d[2]), "+f"(d[3])
        : "r"(a[0]), "r"(a[1]), "r"(a[2]), "r"(a[3]), "r"(b[0]), "r"(b[1]));
}

// ======================= index normalization =======================
__global__ void k_cvt(const int* __restrict__ ei, const int* __restrict__ conn) {
    bool is64 = true;
#pragma unroll
    for (int i = 0; i < 16; i++)
        if (ei[2 * i + 1] != 0) is64 = false;
    int t = blockIdx.x * blockDim.x + threadIdx.x;
    int stride = gridDim.x * blockDim.x;
    if (is64) {
        for (int i = t; i < NEDGE; i += stride) { g_src[i] = ei[2 * i]; g_dst[i] = ei[2 * (NEDGE + i)]; }
        for (int i = t; i < NN; i += stride) g_conn[i] = conn[2 * i];
    } else {
        for (int i = t; i < NEDGE; i += stride) { g_src[i] = ei[i]; g_dst[i] = ei[NEDGE + i]; }
        for (int i = t; i < NN; i += stride) g_conn[i] = conn[i];
    }
}

__global__ void k_zero() {
    size_t i = (size_t)blockIdx.x * blockDim.x + threadIdx.x;
    size_t stride = (size_t)gridDim.x * blockDim.x;
    for (size_t j = i; j < (size_t)NN; j += stride) g_cnt[j] = 0;
    for (size_t j = i; j < (size_t)NGRAPH * 256; j += stride) g_f1[j] = 0.f;
    // pad rows NN..NP of conv2 input must be zero
    for (size_t j = (size_t)NN * C1 + i; j < (size_t)NP * C1; j += stride) {
        g_a2h[j] = __float2bfloat16(0.f);
        g_a2l[j] = __float2bfloat16(0.f);
    }
}

// ======================= CSR build (by dst) =======================
__global__ void k_count() {
    int e = blockIdx.x * blockDim.x + threadIdx.x;
    if (e < NEDGE) atomicAdd(&g_cnt[g_dst[e]], 1);
}

__global__ void k_scan() {   // single block, 1024 threads, 7 nodes/thread
    __shared__ int sh[1024];
    int t = threadIdx.x;
    int base = t * 7;
    int loc[7];
    int s = 0;
#pragma unroll
    for (int i = 0; i < 7; i++) {
        int n = base + i;
        int c = (n < NN) ? g_cnt[n] : 0;
        loc[i] = s;
        s += c;
    }
    sh[t] = s;
    __syncthreads();
    for (int off = 1; off < 1024; off <<= 1) {
        int v = (t >= off) ? sh[t - off] : 0;
        __syncthreads();
        sh[t] += v;
        __syncthreads();
    }
    int ex0 = sh[t] - s;    // exclusive prefix of this thread's chunk
#pragma unroll
    for (int i = 0; i < 7; i++) {
        int n = base + i;
        if (n < NN) {
            g_ofs[n] = ex0 + loc[i];
            g_wofs[n] = ex0 + loc[i];
        }
    }
    if (t == 0) g_ofs[NN] = NEDGE;
}

__global__ void k_fill() {
    int e = blockIdx.x * blockDim.x + threadIdx.x;
    if (e < NEDGE) {
        int pos = atomicAdd(&g_wofs[g_dst[e]], 1);
        g_eidx[pos] = e;
    }
}

// ======================= PE add + bf16 split of A1 =======================
__global__ void k_pe(const float* __restrict__ x, const float* __restrict__ npe,
                     const float* __restrict__ lpe, const float* __restrict__ gpe) {
    int node = blockIdx.x;
    __nv_bfloat16* ah = g_ah + (size_t)node * INDIM;
    __nv_bfloat16* al = g_al_ + (size_t)node * INDIM;
    if (node >= NN) {
        for (int j = threadIdx.x; j < INDIM / 2; j += blockDim.x) {
            ((uint32_t*)ah)[j] = 0u; ((uint32_t*)al)[j] = 0u;
        }
        return;
    }
    int lobe = g_conn[node] - 1;
    int lung = (lobe <= 1) ? 0 : 1;
    const float4* xp = (const float4*)(x + (size_t)node * INDIM);
    const float4* np = (const float4*)(npe + (size_t)(node % NODESP) * INDIM);
    const float4* lp = (const float4*)(lpe + (size_t)lobe * INDIM);
    const float4* gp = (const float4*)(gpe + (size_t)lung * INDIM);
    for (int j = threadIdx.x; j < INDIM / 4; j += blockDim.x) {
        float4 a = xp[j], b = np[j], c = lp[j], d = gp[j];
        float v[4] = { a.x + b.x + c.x + d.x, a.y + b.y + c.y + d.y,
                       a.z + b.z + c.z + d.z, a.w + b.w + c.w + d.w };
        __nv_bfloat16 h[4], l[4];
#pragma unroll
        for (int q = 0; q < 4; q++) {
            h[q] = __float2bfloat16(v[q]);
            l[q] = __float2bfloat16(v[q] - __bfloat162float(h[q]));
        }
        ((__nv_bfloat162*)ah)[2 * j]     = __halves2bfloat162(h[0], h[1]);
        ((__nv_bfloat162*)ah)[2 * j + 1] = __halves2bfloat162(h[2], h[3]);
        ((__nv_bfloat162*)al)[2 * j]     = __halves2bfloat162(l[0], l[1]);
        ((__nv_bfloat162*)al)[2 * j + 1] = __halves2bfloat162(l[2], l[3]);
    }
}

// ======================= weight transpose + split =======================
__global__ void k_wsplit(const float* __restrict__ W, __nv_bfloat16* __restrict__ Th,
                         __nv_bfloat16* __restrict__ Tl, int Nw, int K, int noff) {
    __shared__ float tile[32][33];
    int n0 = blockIdx.x * 32, k0 = blockIdx.y * 32;
    int tx = threadIdx.x, ty = threadIdx.y;  // 32 x 8
#pragma unroll
    for (int r = 0; r < 4; r++)
        tile[ty + r * 8][tx] = W[(size_t)(k0 + ty + r * 8) * Nw + n0 + tx];
    __syncthreads();
#pragma unroll
    for (int r = 0; r < 4; r++) {
        int n = n0 + ty + r * 8;
        float v = tile[tx][ty + r * 8];
        __nv_bfloat16 h = __float2bfloat16(v);
        Th[(size_t)(noff + n) * K + k0 + tx] = h;
        Tl[(size_t)(noff + n) * K + k0 + tx] = __float2bfloat16(v - __bfloat162float(h));
    }
}

__global__ void k_bias(const float* b0, const float* b1, const float* b2, const float* b3,
                       const float* c0, const float* c1_, const float* c2, const float* c3) {
    int t = blockIdx.x * blockDim.x + threadIdx.x;
    if (t < NW1) {
        int w = t >> 11, j = t & 2047;
        g_bc1[t] = (w == 0 ? b0 : w == 1 ? b1 : w == 2 ? b2 : b3)[j];
    }
    if (t < NW2) {
        int w = t >> 6, j = t & 63;
        g_bc2[t] = (w == 0 ? c0 : w == 1 ? c1_ : w == 2 ? c2 : c3)[j];
    }
}

// ======================= mma.sync split-bf16 GEMM (unchanged from R8) =======================
#define ASTAGE 16384
#define STAGE  32768
#define GSMEM  (3 * STAGE)
#define NCHUNK (KTOT / 32)

__device__ __forceinline__ uint32_t swz(int row, int ch) {
    return (uint32_t)(row * 128 + ((ch ^ (row & 7)) << 4));
}

__device__ __forceinline__ void load_stage(uint32_t sbase, int tid, int s, int c,
        const __nv_bfloat16* __restrict__ Ah, const __nv_bfloat16* __restrict__ Al,
        const __nv_bfloat16* __restrict__ Bh, const __nv_bfloat16* __restrict__ Bl,
        int m0, int n0) {
    uint32_t sa = sbase + s * STAGE;
    uint32_t sb = sa + ASTAGE;
    int k0 = c * 32;
#pragma unroll
    for (int i = 0; i < 4; i++) {
        int idx = tid + i * 256;
        int r = idx >> 3, ch = idx & 7;
        const __nv_bfloat16* g = (ch < 4)
            ? (Ah + (size_t)(m0 + r) * KTOT + k0 + ch * 8)
            : (Al + (size_t)(m0 + r) * KTOT + k0 + (ch - 4) * 8);
        cpa16(sa + swz(r, ch), g);
    }
#pragma unroll
    for (int i = 0; i < 4; i++) {
        int idx = tid + i * 256;
        int r = idx >> 3, ch = idx & 7;
        const __nv_bfloat16* g = (ch < 4)
            ? (Bh + (size_t)(n0 + r) * KTOT + k0 + ch * 8)
            : (Bl + (size_t)(n0 + r) * KTOT + k0 + (ch - 4) * 8);
        cpa16(sb + swz(r, ch), g);
    }
    cpa_commit();
}

__global__ void __launch_bounds__(256, 1) mm_gemm(
        const __nv_bfloat16* __restrict__ Ah, const __nv_bfloat16* __restrict__ Al,
        const __nv_bfloat16* __restrict__ Bh, const __nv_bfloat16* __restrict__ Bl,
        const float* __restrict__ bias, float* __restrict__ C, int ldc) {
    extern __shared__ char smem[];
    uint32_t sbase = smem_u32(smem);
    int tid = threadIdx.x, lane = tid & 31, wid = tid >> 5;
    int wm = wid >> 2, wn = wid & 3;
    int m0 = blockIdx.y * 128, n0 = blockIdx.x * 128;

    float acc[4][4][4];
#pragma unroll
    for (int i = 0; i < 4; i++)
#pragma unroll
        for (int j = 0; j < 4; j++)
#pragma unroll
            for (int q = 0; q < 4; q++) acc[i][j][q] = 0.f;

    load_stage(sbase, tid, 0, 0, Ah, Al, Bh, Bl, m0, n0);
    load_stage(sbase, tid, 1, 1, Ah, Al, Bh, Bl, m0, n0);
    load_stage(sbase, tid, 2, 2, Ah, Al, Bh, Bl, m0, n0);

    int a_row_l = (lane & 15);
    int a_chl   = (lane >> 4);
    int b_row_l = (lane & 7) + ((lane >> 4) << 3);
    int b_chl   = ((lane >> 3) & 1);

    for (int c = 0; c < NCHUNK; c++) {
        cpa_wait2();
        __syncthreads();
        uint32_t sa = sbase + (c % 3) * STAGE;
        uint32_t sb = sa + ASTAGE;
#pragma unroll
        for (int ks = 0; ks < 2; ks++) {
            uint32_t a_hi[4][4], a_lo[4][4], b_hi[2][4], b_lo[2][4];
#pragma unroll
            for (int mt = 0; mt < 4; mt++) {
                int row = wm * 64 + mt * 16 + a_row_l;
                ldsm4(a_hi[mt], sa + swz(row, 0 + ks * 2 + a_chl));
                ldsm4(a_lo[mt], sa + swz(row, 4 + ks * 2 + a_chl));
            }
#pragma unroll
            for (int np = 0; np < 2; np++) {
                int row = wn * 32 + np * 16 + b_row_l;
                ldsm4(b_hi[np], sb + swz(row, 0 + ks * 2 + b_chl));
                ldsm4(b_lo[np], sb + swz(row, 4 + ks * 2 + b_chl));
            }
#pragma unroll
            for (int mt = 0; mt < 4; mt++)
#pragma unroll
                for (int nt = 0; nt < 4; nt++) {
                    const uint32_t* bh = &b_hi[nt >> 1][(nt & 1) * 2];
                    const uint32_t* bl = &b_lo[nt >> 1][(nt & 1) * 2];
                    mma16816(acc[mt][nt], a_hi[mt], bh);
                    mma16816(acc[mt][nt], a_hi[mt], bl);
                    mma16816(acc[mt][nt], a_lo[mt], bh);
                }
        }
        __syncthreads();
        if (c + 3 < NCHUNK)
            load_stage(sbase, tid, c % 3, c + 3, Ah, Al, Bh, Bl, m0, n0);
        else
            cpa_commit();
    }

#pragma unroll
    for (int mt = 0; mt < 4; mt++) {
        int row = m0 + wm * 64 + mt * 16 + (lane >> 2);
#pragma unroll
        for (int nt = 0; nt < 4; nt++) {
            int col = n0 + wn * 32 + nt * 8 + (lane & 3) * 2;
            float b0 = bias[col], b1 = bias[col + 1];
            float* p0 = C + (size_t)row * ldc + col;
            p0[0] = acc[mt][nt][0] + b0;
            p0[1] = acc[mt][nt][1] + b1;
            float* p1 = p0 + 8 * ldc;
            p1[0] = acc[mt][nt][2] + b0;
            p1[1] = acc[mt][nt][3] + b1;
        }
    }
}

// ======================= fused conv1 attention (CSR, no atomics) =======================
// g_c1 per-node (stride 8192): q[0:2048] k[2048:4096] v[4096:6144] s[6144:8192]
// Block = one dst node, 256 threads; thread t owns cols t*8..t*8+7 (head = t>>7).
__global__ void __launch_bounds__(256) k_att1() {
    __shared__ float s_part[32][8];
    __shared__ float s_den[2];
    int node = blockIdx.x;
    int tid = threadIdx.x, lane = tid & 31, wid = tid >> 5;
    int tcol = tid * 8;
    int head = tid >> 7;
    int ofs = g_ofs[node], nE = g_ofs[node + 1] - ofs;

    if (tid < 2) s_den[tid] = 0.f;

    // q row into registers
    float qreg[8];
    const float4* qp = (const float4*)(g_c1 + (size_t)node * NW1 + tcol);
    *(float4*)&qreg[0] = qp[0];
    *(float4*)&qreg[4] = qp[1];
    __syncthreads();

    // pass 1: per-edge dots -> exp -> smem denom, ex spilled to g_al1
    for (int t0 = 0; t0 < nE; t0 += 32) {
        int tE = min(32, nE - t0);
        for (int e = 0; e < tE; e++) {
            int eid = g_eidx[ofs + t0 + e];
            int src = g_src[eid];
            const float4* kp = (const float4*)(g_c1 + (size_t)src * NW1 + 2048 + tcol);
            float4 k0 = kp[0], k1 = kp[1];
            float p = qreg[0] * k0.x + qreg[1] * k0.y + qreg[2] * k0.z + qreg[3] * k0.w
                    + qreg[4] * k1.x + qreg[5] * k1.y + qreg[6] * k1.z + qreg[7] * k1.w;
#pragma unroll
            for (int off = 16; off; off >>= 1) p += __shfl_xor_sync(0xffffffffu, p, off);
            if (lane == 0) s_part[e][wid] = p;
        }
        __syncthreads();
        if (tid < tE * 2) {
            int e = tid >> 1, h = tid & 1;
            float d = s_part[e][h * 4 + 0] + s_part[e][h * 4 + 1]
                    + s_part[e][h * 4 + 2] + s_part[e][h * 4 + 3];
            float ex = expf(d * (1.f / 32.f));   // softmax shift-invariant, alpha O(1)
            int eid = g_eidx[ofs + t0 + e];
            g_al1[eid * 2 + h] = ex;
            atomicAdd(&s_den[h], ex);
        }
        __syncthreads();
    }

    float invd = 1.f / (s_den[head] + 1e-16f);

    // pass 2: gather a * v[src]
    float acc[8] = {0.f, 0.f, 0.f, 0.f, 0.f, 0.f, 0.f, 0.f};
    for (int i = 0; i < nE; i++) {
        int eid = g_eidx[ofs + i];
        int src = g_src[eid];
        float a = g_al1[eid * 2 + head] * invd;
        const float4* vp = (const float4*)(g_c1 + (size_t)src * NW1 + 4096 + tcol);
        float4 v0 = vp[0], v1 = vp[1];
        acc[0] += a * v0.x; acc[1] += a * v0.y; acc[2] += a * v0.z; acc[3] += a * v0.w;
        acc[4] += a * v1.x; acc[5] += a * v1.y; acc[6] += a * v1.z; acc[7] += a * v1.w;
    }

    // epilogue: skip + relu -> bf16 hi/lo split (conv2 input)
    const float4* sp = (const float4*)(g_c1 + (size_t)node * NW1 + 6144 + tcol);
    float4 s0 = sp[0], s1 = sp[1];
    float skip[8] = {s0.x, s0.y, s0.z, s0.w, s1.x, s1.y, s1.z, s1.w};
    union { __nv_bfloat16 b[8]; uint4 u; } H, L;
#pragma unroll
    for (int j = 0; j < 8; j++) {
        float v = fmaxf(acc[j] + skip[j], 0.f);
        __nv_bfloat16 h = __float2bfloat16(v);
        H.b[j] = h;
        L.b[j] = __float2bfloat16(v - __bfloat162float(h));
    }
    *(uint4*)(g_a2h + (size_t)node * C1 + tcol) = H.u;
    *(uint4*)(g_a2l + (size_t)node * C1 + tcol) = L.u;
}

// ======================= fused conv2 attention (CSR, no atomics) =======================
// g_c2 per-node (stride 256): q[0:64] k[64:128] v[128:192] s[192:256]. Block = node, 64 threads.
__global__ void __launch_bounds__(64) k_att2() {
    __shared__ float s_part[32][2];
    __shared__ float s_den;
    int node = blockIdx.x;
    int tid = threadIdx.x, lane = tid & 31, wid = tid >> 5;
    int ofs = g_ofs[node], nE = g_ofs[node + 1] - ofs;

    if (tid == 0) s_den = 0.f;
    float qreg = g_c2[(size_t)node * NW2 + tid];
    __syncthreads();

    for (int t0 = 0; t0 < nE; t0 += 32) {
        int tE = min(32, nE - t0);
        for (int e = 0; e < tE; e++) {
            int eid = g_eidx[ofs + t0 + e];
            int src = g_src[eid];
            float p = qreg * g_c2[(size_t)src * NW2 + 64 + tid];
#pragma unroll
            for (int off = 16; off; off >>= 1) p += __shfl_xor_sync(0xffffffffu, p, off);
            if (lane == 0) s_part[e][wid] = p;
        }
        __syncthreads();
        if (tid < tE) {
            float d = s_part[tid][0] + s_part[tid][1];
            float ex = expf(d * 0.125f);
            g_al2[g_eidx[ofs + t0 + tid]] = ex;
            atomicAdd(&s_den, ex);
        }
        __syncthreads();
    }

    float invd = 1.f / (s_den + 1e-16f);
    float acc = 0.f;
    for (int i = 0; i < nE; i++) {
        int eid = g_eidx[ofs + i];
        int src = g_src[eid];
        acc += g_al2[eid] * invd * g_c2[(size_t)src * NW2 + 128 + tid];
    }
    float skip = g_c2[(size_t)node * NW2 + 192 + tid];
    g_out2[(size_t)node * H2 + tid] = fmaxf(acc + skip, 0.f);
}

// ======================= FC head =======================
__global__ void fc1s(const float* __restrict__ W, const float* __restrict__ b) {
    int g = blockIdx.x, ks = blockIdx.y, n = threadIdx.x;
    const float* a = g_out2 + (size_t)g * FCK + ks * 1920;
    const float* w = W + (size_t)ks * 1920 * 256 + n;
    float s0 = (ks == 0) ? b[n] : 0.f, s1 = 0.f, s2 = 0.f, s3 = 0.f;
    for (int k = 0; k < 1920; k += 4) {
        s0 = fmaf(a[k + 0], w[(size_t)(k + 0) * 256], s0);
        s1 = fmaf(a[k + 1], w[(size_t)(k + 1) * 256], s1);
        s2 = fmaf(a[k + 2], w[(size_t)(k + 2) * 256], s2);
        s3 = fmaf(a[k + 3], w[(size_t)(k + 3) * 256], s3);
    }
    atomicAdd(&g_f1[g * 256 + n], (s0 + s1) + (s2 + s3));
}

__global__ void fc(const float* __restrict__ A, const float* __restrict__ W,
                   const float* __restrict__ b, float* __restrict__ C,
                   int N, int K, int relu_out, int relu_in) {
    int m = blockIdx.x, n = threadIdx.x;
    if (n >= N) return;
    const float* a = A + (size_t)m * K;
    float s = b[n];
    for (int k = 0; k < K; k++) {
        float av = a[k];
        if (relu_in) av = fmaxf(av, 0.f);
        s = fmaf(av, W[(size_t)k * N + n], s);
    }
    if (relu_out) s = fmaxf(s, 0.f);
    C[(size_t)m * N + n] = s;
}

// ======================= launch =======================
extern "C" void kernel_launch(void* const* d_in, const int* in_sizes, int n_in,
                              void* d_out, int out_size) {
    const float* x = (const float*)d_in[0];
    const int* ei = (const int*)d_in[1];
    const int* conn = (const int*)d_in[2];
    const float* npe = (const float*)d_in[3];
    const float* lpe = (const float*)d_in[4];
    const float* gpe = (const float*)d_in[5];
    const float* Wq1 = (const float*)d_in[6];  const float* bq1 = (const float*)d_in[7];
    const float* Wk1 = (const float*)d_in[8];  const float* bk1 = (const float*)d_in[9];
    const float* Wv1 = (const float*)d_in[10]; const float* bv1 = (const float*)d_in[11];
    const float* Ws1 = (const float*)d_in[12]; const float* bs1 = (const float*)d_in[13];
    const float* Wq2 = (const float*)d_in[14]; const float* bq2 = (const float*)d_in[15];
    const float* Wk2 = (const float*)d_in[16]; const float* bk2 = (const float*)d_in[17];
    const float* Wv2 = (const float*)d_in[18]; const float* bv2 = (const float*)d_in[19];
    const float* Ws2 = (const float*)d_in[20]; const float* bs2 = (const float*)d_in[21];
    const float* Wf1 = (const float*)d_in[22]; const float* bf1 = (const float*)d_in[23];
    const float* Wf2 = (const float*)d_in[24]; const float* bf2 = (const float*)d_in[25];
    const float* Wf3 = (const float*)d_in[26]; const float* bf3 = (const float*)d_in[27];
    const float* Wf4 = (const float*)d_in[28]; const float* bf4 = (const float*)d_in[29];

    cudaFuncSetAttribute(mm_gemm, cudaFuncAttributeMaxDynamicSharedMemorySize, GSMEM);

    float *c1p, *c2p, *f1p, *f2p, *f3p, *bc1p, *bc2p;
    __nv_bfloat16 *ahp, *alp, *a2hp, *a2lp, *w1hp, *w1lp, *w2hp, *w2lp;
    cudaGetSymbolAddress((void**)&c1p, g_c1);
    cudaGetSymbolAddress((void**)&c2p, g_c2);
    cudaGetSymbolAddress((void**)&f1p, g_f1);
    cudaGetSymbolAddress((void**)&f2p, g_f2);
    cudaGetSymbolAddress((void**)&f3p, g_f3);
    cudaGetSymbolAddress((void**)&bc1p, g_bc1);
    cudaGetSymbolAddress((void**)&bc2p, g_bc2);
    cudaGetSymbolAddress((void**)&ahp, g_ah);
    cudaGetSymbolAddress((void**)&alp, g_al_);
    cudaGetSymbolAddress((void**)&a2hp, g_a2h);
    cudaGetSymbolAddress((void**)&a2lp, g_a2l);
    cudaGetSymbolAddress((void**)&w1hp, g_w1th);
    cudaGetSymbolAddress((void**)&w1lp, g_w1tl);
    cudaGetSymbolAddress((void**)&w2hp, g_w2th);
    cudaGetSymbolAddress((void**)&w2lp, g_w2tl);

    k_cvt<<<256, 256>>>(ei, conn);
    k_zero<<<512, 256>>>();
    k_count<<<(NEDGE + 255) / 256, 256>>>();
    k_scan<<<1, 1024>>>();
    k_fill<<<(NEDGE + 255) / 256, 256>>>();
    k_pe<<<NP, 256>>>(x, npe, lpe, gpe);

    dim3 tb(32, 8);
    dim3 tg1(C1 / 32, INDIM / 32);
    k_wsplit<<<tg1, tb>>>(Wq1, w1hp, w1lp, C1, INDIM, 0);
    k_wsplit<<<tg1, tb>>>(Wk1, w1hp, w1lp, C1, INDIM, 2048);
    k_wsplit<<<tg1, tb>>>(Wv1, w1hp, w1lp, C1, INDIM, 4096);
    k_wsplit<<<tg1, tb>>>(Ws1, w1hp, w1lp, C1, INDIM, 6144);
    dim3 tg2(H2 / 32, C1 / 32);
    k_wsplit<<<tg2, tb>>>(Wq2, w2hp, w2lp, H2, C1, 0);
    k_wsplit<<<tg2, tb>>>(Wk2, w2hp, w2lp, H2, C1, 64);
    k_wsplit<<<tg2, tb>>>(Wv2, w2hp, w2lp, H2, C1, 128);
    k_wsplit<<<tg2, tb>>>(Ws2, w2hp, w2lp, H2, C1, 192);
    k_bias<<<(NW1 + 255) / 256, 256>>>(bq1, bk1, bv1, bs1, bq2, bk2, bv2, bs2);

    // conv1: fused 4-weight GEMM  [NP,2048] x [2048,8192]
    mm_gemm<<<dim3(NW1 / 128, NP / 128), 256, GSMEM>>>(ahp, alp, w1hp, w1lp, bc1p, c1p, NW1);

    // conv1 attention (fused softmax + gather + epilogue + split)
    k_att1<<<NN, 256>>>();

    // conv2: fused 4-weight GEMM  [NP,2048] x [2048,256]
    mm_gemm<<<dim3(NW2 / 128, NP / 128), 256, GSMEM>>>(a2hp, a2lp, w2hp, w2lp, bc2p, c2p, NW2);

    // conv2 attention
    k_att2<<<NN, 64>>>();

    fc1s<<<dim3(NGRAPH, 14), 256>>>(Wf1, bf1);
    fc<<<NGRAPH, 128>>>(f1p, Wf2, bf2, f2p, 128, 256, 1, 1);
    fc<<<NGRAPH, 64>>>(f2p, Wf3, bf3, f3p, 64, 128, 1, 0);
    fc<<<NGRAPH, 32>>>(f3p, Wf4, bf4, (float*)d_out, OUTD, 64, 0, 0);
}

// round 12
// speedup vs baseline: 5.6298x; 1.3102x over previous
#include <cuda_runtime.h>
#include <cuda_fp16.h>
#include <cstdint>

#define NGRAPH 16
#define NODESP 420
#define NN     6720
#define NP     6784    // padded to 53*128
#define NEDGE  53760
#define INDIM  2048
#define C1     2048
#define H1     1024
#define H2     64
#define OUTD   18
#define FCK    26880
#define NW1    8192    // 4 fused conv1 weight mats
#define NW2    256     // 4 fused conv2 weight mats
#define KTOT   2048

// ======================= device scratch =======================
__device__ float g_c1[(size_t)NP * NW1];            // fused q|k|v|s conv1 out
__device__ float g_al1[NEDGE * 2];                  // per-edge exp (spill)
__device__ float g_c2[(size_t)NP * NW2];            // fused q|k|v|s conv2 out
__device__ float g_out2[(size_t)NN * H2];
__device__ float g_al2[NEDGE];
__device__ float g_f1[NGRAPH * 256];
__device__ float g_f2[NGRAPH * 128];
__device__ float g_f3[NGRAPH * 64];
__device__ int   g_src[NEDGE];
__device__ int   g_dst[NEDGE];
__device__ int   g_conn[NN];
__device__ int   g_ofs[NN + 1];
__device__ int   g_wofs[NN];
__device__ int   g_eidx[NEDGE];
__device__ __half g_ah[(size_t)NP * INDIM];   // A1 hi
__device__ __half g_al_[(size_t)NP * INDIM];  // A1 lo
__device__ __half g_a2h[(size_t)NP * C1];     // A2 hi
__device__ __half g_a2l[(size_t)NP * C1];     // A2 lo
__device__ __half g_w1t[(size_t)NW1 * INDIM]; // W1^T fp16 [n][k]
__device__ __half g_w2t[(size_t)NW2 * C1];
__device__ float g_bc1[NW1];
__device__ float g_bc2[NW2];

// ======================= sm_80-baseline PTX wrappers =======================
__device__ __forceinline__ uint32_t smem_u32(const void* p) {
    uint32_t a;
    asm("{ .reg .u64 t; cvta.to.shared.u64 t, %1; cvt.u32.u64 %0, t; }" : "=r"(a) : "l"(p));
    return a;
}
__device__ __forceinline__ void cpa16(uint32_t s, const void* g) {
    asm volatile("cp.async.cg.shared.global [%0], [%1], 16;" :: "r"(s), "l"(g));
}
__device__ __forceinline__ void cpa_commit() {
    asm volatile("cp.async.commit_group;" ::: "memory");
}
__device__ __forceinline__ void cpa_wait2() {
    asm volatile("cp.async.wait_group 2;" ::: "memory");
}
__device__ __forceinline__ void ldsm4(uint32_t* r, uint32_t addr) {
    asm volatile("ldmatrix.sync.aligned.m8n8.x4.shared.b16 {%0,%1,%2,%3}, [%4];"
        : "=r"(r[0]), "=r"(r[1]), "=r"(r[2]), "=r"(r[3]) : "r"(addr));
}
__device__ __forceinline__ void mma16816(float* d, const uint32_t* a, const uint32_t* b) {
    asm volatile("mma.sync.aligned.m16n8k16.row.col.f32.f16.f16.f32 "
        "{%0,%1,%2,%3}, {%4,%5,%6,%7}, {%8,%9}, {%0,%1,%2,%3};"
        : "+f"(d[0]), "+f"(d[1]), "+f"(d[2]), "+f"(d[3])
        : "r"(a[0]), "r"(a[1]), "r"(a[2]), "r"(a[3]), "r"(b[0]), "r"(b[1]));
}

// ===== launch 1: index normalization + all zero-init =====
__global__ void k_cvt(const int* __restrict__ ei, const int* __restrict__ conn) {
    bool is64 = true;
#pragma unroll
    for (int i = 0; i < 16; i++)
        if (ei[2 * i + 1] != 0) is64 = false;
    int t = blockIdx.x * blockDim.x + threadIdx.x;
    int stride = gridDim.x * blockDim.x;
    if (is64) {
        for (int i = t; i < NEDGE; i += stride) { g_src[i] = ei[2 * i]; g_dst[i] = ei[2 * (NEDGE + i)]; }
        for (int i = t; i < NN; i += stride) g_conn[i] = conn[2 * i];
    } else {
        for (int i = t; i < NEDGE; i += stride) { g_src[i] = ei[i]; g_dst[i] = ei[NEDGE + i]; }
        for (int i = t; i < NN; i += stride) g_conn[i] = conn[i];
    }
    for (int i = t; i < NGRAPH * 256; i += stride) g_f1[i] = 0.f;
    // pad rows NN..NP of conv2 input must stay zero
    const __half z = __float2half(0.f);
    for (size_t j = (size_t)NN * C1 + t; j < (size_t)NP * C1; j += stride) {
        g_a2h[j] = z;
        g_a2l[j] = z;
    }
}

// ===== launch 2: smem histogram + scan -> CSR offsets =====
__global__ void k_scan() {
    __shared__ int scnt[NN];
    __shared__ int sh[1024];
    int t = threadIdx.x;
    for (int i = t; i < NN; i += 1024) scnt[i] = 0;
    __syncthreads();
    for (int e = t; e < NEDGE; e += 1024) atomicAdd(&scnt[g_dst[e]], 1);
    __syncthreads();
    int base = t * 7;
    int loc[7];
    int s = 0;
#pragma unroll
    for (int i = 0; i < 7; i++) {
        int n = base + i;
        int c = (n < NN) ? scnt[n] : 0;
        loc[i] = s;
        s += c;
    }
    sh[t] = s;
    __syncthreads();
    for (int off = 1; off < 1024; off <<= 1) {
        int v = (t >= off) ? sh[t - off] : 0;
        __syncthreads();
        sh[t] += v;
        __syncthreads();
    }
    int ex0 = sh[t] - s;
#pragma unroll
    for (int i = 0; i < 7; i++) {
        int n = base + i;
        if (n < NN) {
            g_ofs[n] = ex0 + loc[i];
            g_wofs[n] = ex0 + loc[i];
        }
    }
    if (t == 0) g_ofs[NN] = NEDGE;
}

// ===== launch 3: CSR fill + fused bias packing =====
__global__ void k_fillb(const float* b0, const float* b1, const float* b2, const float* b3,
                        const float* c0, const float* c1_, const float* c2, const float* c3) {
    int e = blockIdx.x * blockDim.x + threadIdx.x;
    if (e < NEDGE) {
        int pos = atomicAdd(&g_wofs[g_dst[e]], 1);
        g_eidx[pos] = e;
    }
    if (e < NW1) {
        int w = e >> 11, j = e & 2047;
        g_bc1[e] = (w == 0 ? b0 : w == 1 ? b1 : w == 2 ? b2 : b3)[j];
    }
    if (e < NW2) {
        int w = e >> 6, j = e & 63;
        g_bc2[e] = (w == 0 ? c0 : w == 1 ? c1_ : w == 2 ? c2 : c3)[j];
    }
}

// ===== launch 4: PE add + fp16 hi/lo split of A1 =====
__global__ void k_pe(const float* __restrict__ x, const float* __restrict__ npe,
                     const float* __restrict__ lpe, const float* __restrict__ gpe) {
    int node = blockIdx.x;
    __half* ah = g_ah + (size_t)node * INDIM;
    __half* al = g_al_ + (size_t)node * INDIM;
    if (node >= NN) {
        for (int j = threadIdx.x; j < INDIM / 2; j += blockDim.x) {
            ((uint32_t*)ah)[j] = 0u; ((uint32_t*)al)[j] = 0u;
        }
        return;
    }
    int lobe = g_conn[node] - 1;
    int lung = (lobe <= 1) ? 0 : 1;
    const float4* xp = (const float4*)(x + (size_t)node * INDIM);
    const float4* np = (const float4*)(npe + (size_t)(node % NODESP) * INDIM);
    const float4* lp = (const float4*)(lpe + (size_t)lobe * INDIM);
    const float4* gp = (const float4*)(gpe + (size_t)lung * INDIM);
    for (int j = threadIdx.x; j < INDIM / 4; j += blockDim.x) {
        float4 a = xp[j], b = np[j], c = lp[j], d = gp[j];
        float v[4] = { a.x + b.x + c.x + d.x, a.y + b.y + c.y + d.y,
                       a.z + b.z + c.z + d.z, a.w + b.w + c.w + d.w };
        __half h[4], l[4];
#pragma unroll
        for (int q = 0; q < 4; q++) {
            h[q] = __float2half_rn(v[q]);
            l[q] = __float2half_rn(v[q] - __half2float(h[q]));
        }
        ((__half2*)ah)[2 * j]     = __halves2half2(h[0], h[1]);
        ((__half2*)ah)[2 * j + 1] = __halves2half2(h[2], h[3]);
        ((__half2*)al)[2 * j]     = __halves2half2(l[0], l[1]);
        ((__half2*)al)[2 * j + 1] = __halves2half2(l[2], l[3]);
    }
}

// ===== launch 5: fused weight transpose -> fp16 (all 8 matrices) =====
__global__ void k_wsplit_all(const float* Wq1, const float* Wk1, const float* Wv1, const float* Ws1,
                             const float* Wq2, const float* Wk2, const float* Wv2, const float* Ws2) {
    __shared__ float tile[32][33];
    int z = blockIdx.z;
    const float* W;
    __half* T;
    int Nw, K, n0, noff;
    if (z < 4) {
        W = (z == 0) ? Wq1 : (z == 1) ? Wk1 : (z == 2) ? Wv1 : Ws1;
        T = g_w1t; Nw = C1; K = INDIM;
        n0 = blockIdx.x * 32; noff = z * 2048;
    } else {
        if (blockIdx.x >= 8) return;
        int mat = blockIdx.x >> 1;
        W = (mat == 0) ? Wq2 : (mat == 1) ? Wk2 : (mat == 2) ? Wv2 : Ws2;
        T = g_w2t; Nw = H2; K = C1;
        n0 = (blockIdx.x & 1) * 32; noff = mat * 64;
    }
    int k0 = blockIdx.y * 32;
    int tx = threadIdx.x, ty = threadIdx.y;  // 32 x 8
#pragma unroll
    for (int r = 0; r < 4; r++)
        tile[ty + r * 8][tx] = W[(size_t)(k0 + ty + r * 8) * Nw + n0 + tx];
    __syncthreads();
#pragma unroll
    for (int r = 0; r < 4; r++) {
        int n = n0 + ty + r * 8;
        T[(size_t)(noff + n) * K + k0 + tx] = __float2half_rn(tile[tx][ty + r * 8]);
    }
}

// ======================= mma.sync 2-term fp16 GEMM =======================
// C[m][n] = sum_k (Ah+Al)[m][k]*B[n][k] + bias[n], K=2048.
// BM=128, BN=128, BK=32. 8 warps in 2(M)x4(N); warp tile 64x32.
// A stage rows: 128B = [Ah 64B | Al 64B] swizzled; B stage rows: 128B, chunks 0..3 used.
#define ASTAGE 16384
#define STAGE  32768
#define GSMEM  (3 * STAGE)
#define NCHUNK (KTOT / 32)

__device__ __forceinline__ uint32_t swz(int row, int ch) {
    return (uint32_t)(row * 128 + ((ch ^ (row & 7)) << 4));
}

__device__ __forceinline__ void load_stage(uint32_t sbase, int tid, int s, int c,
        const __half* __restrict__ Ah, const __half* __restrict__ Al,
        const __half* __restrict__ B, int m0, int n0) {
    uint32_t sa = sbase + s * STAGE;
    uint32_t sb = sa + ASTAGE;
    int k0 = c * 32;
#pragma unroll
    for (int i = 0; i < 4; i++) {
        int idx = tid + i * 256;          // 1024 ops: A hi|lo
        int r = idx >> 3, ch = idx & 7;
        const __half* g = (ch < 4)
            ? (Ah + (size_t)(m0 + r) * KTOT + k0 + ch * 8)
            : (Al + (size_t)(m0 + r) * KTOT + k0 + (ch - 4) * 8);
        cpa16(sa + swz(r, ch), g);
    }
#pragma unroll
    for (int i = 0; i < 2; i++) {
        int idx = tid + i * 256;          // 512 ops: B (chunks 0..3)
        int r = idx >> 2, ch = idx & 3;
        cpa16(sb + swz(r, ch), B + (size_t)(n0 + r) * KTOT + k0 + ch * 8);
    }
    cpa_commit();
}

__global__ void __launch_bounds__(256, 1) mm_gemm(
        const __half* __restrict__ Ah, const __half* __restrict__ Al,
        const __half* __restrict__ B,
        const float* __restrict__ bias, float* __restrict__ C, int ldc) {
    extern __shared__ char smem[];
    uint32_t sbase = smem_u32(smem);
    int tid = threadIdx.x, lane = tid & 31, wid = tid >> 5;
    int wm = wid >> 2, wn = wid & 3;
    int m0 = blockIdx.y * 128, n0 = blockIdx.x * 128;

    float acc[4][4][4];
#pragma unroll
    for (int i = 0; i < 4; i++)
#pragma unroll
        for (int j = 0; j < 4; j++)
#pragma unroll
            for (int q = 0; q < 4; q++) acc[i][j][q] = 0.f;

    load_stage(sbase, tid, 0, 0, Ah, Al, B, m0, n0);
    load_stage(sbase, tid, 1, 1, Ah, Al, B, m0, n0);
    load_stage(sbase, tid, 2, 2, Ah, Al, B, m0, n0);

    int a_row_l = (lane & 15);
    int a_chl   = (lane >> 4);
    int b_row_l = (lane & 7) + ((lane >> 4) << 3);
    int b_chl   = ((lane >> 3) & 1);

    for (int c = 0; c < NCHUNK; c++) {
        cpa_wait2();
        __syncthreads();
        uint32_t sa = sbase + (c % 3) * STAGE;
        uint32_t sb = sa + ASTAGE;
#pragma unroll
        for (int ks = 0; ks < 2; ks++) {
            uint32_t a_hi[4][4], a_lo[4][4], b_f[2][4];
#pragma unroll
            for (int mt = 0; mt < 4; mt++) {
                int row = wm * 64 + mt * 16 + a_row_l;
                ldsm4(a_hi[mt], sa + swz(row, 0 + ks * 2 + a_chl));
                ldsm4(a_lo[mt], sa + swz(row, 4 + ks * 2 + a_chl));
            }
#pragma unroll
            for (int np = 0; np < 2; np++) {
                int row = wn * 32 + np * 16 + b_row_l;
                ldsm4(b_f[np], sb + swz(row, ks * 2 + b_chl));
            }
#pragma unroll
            for (int mt = 0; mt < 4; mt++)
#pragma unroll
                for (int nt = 0; nt < 4; nt++) {
                    const uint32_t* bf = &b_f[nt >> 1][(nt & 1) * 2];
                    mma16816(acc[mt][nt], a_hi[mt], bf);
                    mma16816(acc[mt][nt], a_lo[mt], bf);
                }
        }
        __syncthreads();
        if (c + 3 < NCHUNK)
            load_stage(sbase, tid, c % 3, c + 3, Ah, Al, B, m0, n0);
        else
            cpa_commit();
    }

#pragma unroll
    for (int mt = 0; mt < 4; mt++) {
        int row = m0 + wm * 64 + mt * 16 + (lane >> 2);
#pragma unroll
        for (int nt = 0; nt < 4; nt++) {
            int col = n0 + wn * 32 + nt * 8 + (lane & 3) * 2;
            float b0 = bias[col], b1 = bias[col + 1];
            float* p0 = C + (size_t)row * ldc + col;
            p0[0] = acc[mt][nt][0] + b0;
            p0[1] = acc[mt][nt][1] + b1;
            float* p1 = p0 + 8 * ldc;
            p1[0] = acc[mt][nt][2] + b0;
            p1[1] = acc[mt][nt][3] + b1;
        }
    }
}

// ======================= fused conv1 attention (CSR, no atomics) =======================
// g_c1 per-node (stride 8192): q[0:2048] k[2048:4096] v[4096:6144] s[6144:8192]
__global__ void __launch_bounds__(256) k_att1() {
    __shared__ float s_part[32][8];
    __shared__ float s_den[2];
    int node = blockIdx.x;
    int tid = threadIdx.x, lane = tid & 31, wid = tid >> 5;
    int tcol = tid * 8;
    int head = tid >> 7;
    int ofs = g_ofs[node], nE = g_ofs[node + 1] - ofs;

    if (tid < 2) s_den[tid] = 0.f;

    float qreg[8];
    const float4* qp = (const float4*)(g_c1 + (size_t)node * NW1 + tcol);
    *(float4*)&qreg[0] = qp[0];
    *(float4*)&qreg[4] = qp[1];
    __syncthreads();

    for (int t0 = 0; t0 < nE; t0 += 32) {
        int tE = min(32, nE - t0);
        for (int e = 0; e < tE; e++) {
            int eid = g_eidx[ofs + t0 + e];
            int src = g_src[eid];
            const float4* kp = (const float4*)(g_c1 + (size_t)src * NW1 + 2048 + tcol);
            float4 k0 = kp[0], k1 = kp[1];
            float p = qreg[0] * k0.x + qreg[1] * k0.y + qreg[2] * k0.z + qreg[3] * k0.w
                    + qreg[4] * k1.x + qreg[5] * k1.y + qreg[6] * k1.z + qreg[7] * k1.w;
#pragma unroll
            for (int off = 16; off; off >>= 1) p += __shfl_xor_sync(0xffffffffu, p, off);
            if (lane == 0) s_part[e][wid] = p;
        }
        __syncthreads();
        if (tid < tE * 2) {
            int e = tid >> 1, h = tid & 1;
            float d = s_part[e][h * 4 + 0] + s_part[e][h * 4 + 1]
                    + s_part[e][h * 4 + 2] + s_part[e][h * 4 + 3];
            float ex = expf(d * (1.f / 32.f));   // softmax shift-invariant, alpha O(1)
            int eid = g_eidx[ofs + t0 + e];
            g_al1[eid * 2 + h] = ex;
            atomicAdd(&s_den[h], ex);
        }
        __syncthreads();
    }

    float invd = 1.f / (s_den[head] + 1e-16f);

    float acc[8] = {0.f, 0.f, 0.f, 0.f, 0.f, 0.f, 0.f, 0.f};
    for (int i = 0; i < nE; i++) {
        int eid = g_eidx[ofs + i];
        int src = g_src[eid];
        float a = g_al1[eid * 2 + head] * invd;
        const float4* vp = (const float4*)(g_c1 + (size_t)src * NW1 + 4096 + tcol);
        float4 v0 = vp[0], v1 = vp[1];
        acc[0] += a * v0.x; acc[1] += a * v0.y; acc[2] += a * v0.z; acc[3] += a * v0.w;
        acc[4] += a * v1.x; acc[5] += a * v1.y; acc[6] += a * v1.z; acc[7] += a * v1.w;
    }

    const float4* sp = (const float4*)(g_c1 + (size_t)node * NW1 + 6144 + tcol);
    float4 s0 = sp[0], s1 = sp[1];
    float skip[8] = {s0.x, s0.y, s0.z, s0.w, s1.x, s1.y, s1.z, s1.w};
    union { __half b[8]; uint4 u; } H, L;
#pragma unroll
    for (int j = 0; j < 8; j++) {
        float v = fmaxf(acc[j] + skip[j], 0.f);
        __half h = __float2half_rn(v);
        H.b[j] = h;
        L.b[j] = __float2half_rn(v - __half2float(h));
    }
    *(uint4*)(g_a2h + (size_t)node * C1 + tcol) = H.u;
    *(uint4*)(g_a2l + (size_t)node * C1 + tcol) = L.u;
}

// ======================= fused conv2 attention (CSR, no atomics) =======================
__global__ void __launch_bounds__(64) k_att2() {
    __shared__ float s_part[32][2];
    __shared__ float s_den;
    int node = blockIdx.x;
    int tid = threadIdx.x, lane = tid & 31, wid = tid >> 5;
    int ofs = g_ofs[node], nE = g_ofs[node + 1] - ofs;

    if (tid == 0) s_den = 0.f;
    float qreg = g_c2[(size_t)node * NW2 + tid];
    __syncthreads();

    for (int t0 = 0; t0 < nE; t0 += 32) {
        int tE = min(32, nE - t0);
        for (int e = 0; e < tE; e++) {
            int eid = g_eidx[ofs + t0 + e];
            int src = g_src[eid];
            float p = qreg * g_c2[(size_t)src * NW2 + 64 + tid];
#pragma unroll
            for (int off = 16; off; off >>= 1) p += __shfl_xor_sync(0xffffffffu, p, off);
            if (lane == 0) s_part[e][wid] = p;
        }
        __syncthreads();
        if (tid < tE) {
            float d = s_part[tid][0] + s_part[tid][1];
            float ex = expf(d * 0.125f);
            g_al2[g_eidx[ofs + t0 + tid]] = ex;
            atomicAdd(&s_den, ex);
        }
        __syncthreads();
    }

    float invd = 1.f / (s_den + 1e-16f);
    float acc = 0.f;
    for (int i = 0; i < nE; i++) {
        int eid = g_eidx[ofs + i];
        int src = g_src[eid];
        acc += g_al2[eid] * invd * g_c2[(size_t)src * NW2 + 128 + tid];
    }
    float skip = g_c2[(size_t)node * NW2 + 192 + tid];
    g_out2[(size_t)node * H2 + tid] = fmaxf(acc + skip, 0.f);
}

// ======================= FC head =======================
__global__ void fc1s(const float* __restrict__ W, const float* __restrict__ b) {
    int g = blockIdx.x, ks = blockIdx.y, n = threadIdx.x;
    const float* a = g_out2 + (size_t)g * FCK + ks * 1920;
    const float* w = W + (size_t)ks * 1920 * 256 + n;
    float s0 = (ks == 0) ? b[n] : 0.f, s1 = 0.f, s2 = 0.f, s3 = 0.f;
    for (int k = 0; k < 1920; k += 4) {
        s0 = fmaf(a[k + 0], w[(size_t)(k + 0) * 256], s0);
        s1 = fmaf(a[k + 1], w[(size_t)(k + 1) * 256], s1);
        s2 = fmaf(a[k + 2], w[(size_t)(k + 2) * 256], s2);
        s3 = fmaf(a[k + 3], w[(size_t)(k + 3) * 256], s3);
    }
    atomicAdd(&g_f1[g * 256 + n], (s0 + s1) + (s2 + s3));
}

__global__ void fc(const float* __restrict__ A, const float* __restrict__ W,
                   const float* __restrict__ b, float* __restrict__ C,
                   int N, int K, int relu_out, int relu_in) {
    int m = blockIdx.x, n = threadIdx.x;
    if (n >= N) return;
    const float* a = A + (size_t)m * K;
    float s = b[n];
    for (int k = 0; k < K; k++) {
        float av = a[k];
        if (relu_in) av = fmaxf(av, 0.f);
        s = fmaf(av, W[(size_t)k * N + n], s);
    }
    if (relu_out) s = fmaxf(s, 0.f);
    C[(size_t)m * N + n] = s;
}

// ======================= launch =======================
extern "C" void kernel_launch(void* const* d_in, const int* in_sizes, int n_in,
                              void* d_out, int out_size) {
    const float* x = (const float*)d_in[0];
    const int* ei = (const int*)d_in[1];
    const int* conn = (const int*)d_in[2];
    const float* npe = (const float*)d_in[3];
    const float* lpe = (const float*)d_in[4];
    const float* gpe = (const float*)d_in[5];
    const float* Wq1 = (const float*)d_in[6];  const float* bq1 = (const float*)d_in[7];
    const float* Wk1 = (const float*)d_in[8];  const float* bk1 = (const float*)d_in[9];
    const float* Wv1 = (const float*)d_in[10]; const float* bv1 = (const float*)d_in[11];
    const float* Ws1 = (const float*)d_in[12]; const float* bs1 = (const float*)d_in[13];
    const float* Wq2 = (const float*)d_in[14]; const float* bq2 = (const float*)d_in[15];
    const float* Wk2 = (const float*)d_in[16]; const float* bk2 = (const float*)d_in[17];
    const float* Wv2 = (const float*)d_in[18]; const float* bv2 = (const float*)d_in[19];
    const float* Ws2 = (const float*)d_in[20]; const float* bs2 = (const float*)d_in[21];
    const float* Wf1 = (const float*)d_in[22]; const float* bf1 = (const float*)d_in[23];
    const float* Wf2 = (const float*)d_in[24]; const float* bf2 = (const float*)d_in[25];
    const float* Wf3 = (const float*)d_in[26]; const float* bf3 = (const float*)d_in[27];
    const float* Wf4 = (const float*)d_in[28]; const float* bf4 = (const float*)d_in[29];

    cudaFuncSetAttribute(mm_gemm, cudaFuncAttributeMaxDynamicSharedMemorySize, GSMEM);

    float *c1p, *c2p, *f1p, *f2p, *f3p, *bc1p, *bc2p;
    __half *ahp, *alp, *a2hp, *a2lp, *w1tp, *w2tp;
    cudaGetSymbolAddress((void**)&c1p, g_c1);
    cudaGetSymbolAddress((void**)&c2p, g_c2);
    cudaGetSymbolAddress((void**)&f1p, g_f1);
    cudaGetSymbolAddress((void**)&f2p, g_f2);
    cudaGetSymbolAddress((void**)&f3p, g_f3);
    cudaGetSymbolAddress((void**)&bc1p, g_bc1);
    cudaGetSymbolAddress((void**)&bc2p, g_bc2);
    cudaGetSymbolAddress((void**)&ahp, g_ah);
    cudaGetSymbolAddress((void**)&alp, g_al_);
    cudaGetSymbolAddress((void**)&a2hp, g_a2h);
    cudaGetSymbolAddress((void**)&a2lp, g_a2l);
    cudaGetSymbolAddress((void**)&w1tp, g_w1t);
    cudaGetSymbolAddress((void**)&w2tp, g_w2t);

    // launches 1-5 (prep) — mm_gemm conv1 is launch #6 for ncu (-s 5 -c 1)
    k_cvt<<<256, 256>>>(ei, conn);
    k_scan<<<1, 1024>>>();
    k_fillb<<<(NEDGE + 255) / 256, 256>>>(bq1, bk1, bv1, bs1, bq2, bk2, bv2, bs2);
    k_pe<<<NP, 256>>>(x, npe, lpe, gpe);
    k_wsplit_all<<<dim3(64, 64, 5), dim3(32, 8)>>>(Wq1, Wk1, Wv1, Ws1, Wq2, Wk2, Wv2, Ws2);

    // conv1: fused 4-weight GEMM  [NP,2048] x [2048,8192]
    mm_gemm<<<dim3(NW1 / 128, NP / 128), 256, GSMEM>>>(ahp, alp, w1tp, bc1p, c1p, NW1);

    k_att1<<<NN, 256>>>();

    // conv2: fused 4-weight GEMM  [NP,2048] x [2048,256]
    mm_gemm<<<dim3(NW2 / 128, NP / 128), 256, GSMEM>>>(a2hp, a2lp, w2tp, bc2p, c2p, NW2);

    k_att2<<<NN, 64>>>();

    fc1s<<<dim3(NGRAPH, 14), 256>>>(Wf1, bf1);
    fc<<<NGRAPH, 128>>>(f1p, Wf2, bf2, f2p, 128, 256, 1, 1);
    fc<<<NGRAPH, 64>>>(f2p, Wf3, bf3, f3p, 64, 128, 1, 0);
    fc<<<NGRAPH, 32>>>(f3p, Wf4, bf4, (float*)d_out, OUTD, 64, 0, 0);
}

// round 13
// speedup vs baseline: 9.0882x; 1.6143x over previous
#include <cuda_runtime.h>
#include <cuda_fp16.h>
#include <cstdint>

#define NGRAPH 16
#define NODESP 420
#define NN     6720
#define NP     6784    // padded to 53*128
#define NEDGE  53760
#define INDIM  2048
#define C1     2048
#define H1     1024
#define H2     64
#define OUTD   18
#define FCK    26880
#define NW1    8192    // 4 fused conv1 weight mats
#define NW2    256     // 4 fused conv2 weight mats
#define KTOT   2048

// ======================= device scratch =======================
__device__ float g_c1[(size_t)NP * NW1];            // fused q|k|v|s conv1 out
__device__ float g_al1[NEDGE * 2];                  // per-edge exp (spill)
__device__ float g_c2[(size_t)NP * NW2];            // fused q|k|v|s conv2 out
__device__ float g_out2[(size_t)NN * H2];
__device__ float g_al2[NEDGE];
__device__ float g_f1[NGRAPH * 256];
__device__ float g_f2[NGRAPH * 128];
__device__ float g_f3[NGRAPH * 64];
__device__ int   g_src[NEDGE];
__device__ int   g_dst[NEDGE];
__device__ int   g_conn[NN];
__device__ int   g_ofs[NN + 1];
__device__ int   g_wofs[NN];
__device__ int   g_eidx[NEDGE];
__device__ __half g_a1[(size_t)NP * INDIM];   // A1 fp16
__device__ __half g_a2[(size_t)NP * C1];      // A2 fp16
__device__ __half g_w1t[(size_t)NW1 * INDIM]; // W1^T fp16 [n][k]
__device__ __half g_w2t[(size_t)NW2 * C1];
__device__ float g_bc1[NW1];
__device__ float g_bc2[NW2];

// ======================= sm_80-baseline PTX wrappers =======================
__device__ __forceinline__ uint32_t smem_u32(const void* p) {
    uint32_t a;
    asm("{ .reg .u64 t; cvta.to.shared.u64 t, %1; cvt.u32.u64 %0, t; }" : "=r"(a) : "l"(p));
    return a;
}
__device__ __forceinline__ void cpa16(uint32_t s, const void* g) {
    asm volatile("cp.async.cg.shared.global [%0], [%1], 16;" :: "r"(s), "l"(g));
}
__device__ __forceinline__ void cpa_commit() {
    asm volatile("cp.async.commit_group;" ::: "memory");
}
__device__ __forceinline__ void cpa_wait2() {
    asm volatile("cp.async.wait_group 2;" ::: "memory");
}
__device__ __forceinline__ void ldsm4(uint32_t* r, uint32_t addr) {
    asm volatile("ldmatrix.sync.aligned.m8n8.x4.shared.b16 {%0,%1,%2,%3}, [%4];"
        : "=r"(r[0]), "=r"(r[1]), "=r"(r[2]), "=r"(r[3]) : "r"(addr));
}
__device__ __forceinline__ void mma16816(float* d, const uint32_t* a, const uint32_t* b) {
    asm volatile("mma.sync.aligned.m16n8k16.row.col.f32.f16.f16.f32 "
        "{%0,%1,%2,%3}, {%4,%5,%6,%7}, {%8,%9}, {%0,%1,%2,%3};"
        : "+f"(d[0]), "+f"(d[1]), "+f"(d[2]), "+f"(d[3])
        : "r"(a[0]), "r"(a[1]), "r"(a[2]), "r"(a[3]), "r"(b[0]), "r"(b[1]));
}

// ===== launch 1: index normalization + all zero-init =====
__global__ void k_cvt(const int* __restrict__ ei, const int* __restrict__ conn) {
    bool is64 = true;
#pragma unroll
    for (int i = 0; i < 16; i++)
        if (ei[2 * i + 1] != 0) is64 = false;
    int t = blockIdx.x * blockDim.x + threadIdx.x;
    int stride = gridDim.x * blockDim.x;
    if (is64) {
        for (int i = t; i < NEDGE; i += stride) { g_src[i] = ei[2 * i]; g_dst[i] = ei[2 * (NEDGE + i)]; }
        for (int i = t; i < NN; i += stride) g_conn[i] = conn[2 * i];
    } else {
        for (int i = t; i < NEDGE; i += stride) { g_src[i] = ei[i]; g_dst[i] = ei[NEDGE + i]; }
        for (int i = t; i < NN; i += stride) g_conn[i] = conn[i];
    }
    for (int i = t; i < NGRAPH * 256; i += stride) g_f1[i] = 0.f;
    // pad rows NN..NP of conv2 input must stay zero
    const __half z = __float2half(0.f);
    for (size_t j = (size_t)NN * C1 + t; j < (size_t)NP * C1; j += stride)
        g_a2[j] = z;
}

// ===== launch 2: smem histogram + scan -> CSR offsets =====
__global__ void k_scan() {
    __shared__ int scnt[NN];
    __shared__ int sh[1024];
    int t = threadIdx.x;
    for (int i = t; i < NN; i += 1024) scnt[i] = 0;
    __syncthreads();
    for (int e = t; e < NEDGE; e += 1024) atomicAdd(&scnt[g_dst[e]], 1);
    __syncthreads();
    int base = t * 7;
    int loc[7];
    int s = 0;
#pragma unroll
    for (int i = 0; i < 7; i++) {
        int n = base + i;
        int c = (n < NN) ? scnt[n] : 0;
        loc[i] = s;
        s += c;
    }
    sh[t] = s;
    __syncthreads();
    for (int off = 1; off < 1024; off <<= 1) {
        int v = (t >= off) ? sh[t - off] : 0;
        __syncthreads();
        sh[t] += v;
        __syncthreads();
    }
    int ex0 = sh[t] - s;
#pragma unroll
    for (int i = 0; i < 7; i++) {
        int n = base + i;
        if (n < NN) {
            g_ofs[n] = ex0 + loc[i];
            g_wofs[n] = ex0 + loc[i];
        }
    }
    if (t == 0) g_ofs[NN] = NEDGE;
}

// ===== launch 3: CSR fill + fused bias packing =====
__global__ void k_fillb(const float* b0, const float* b1, const float* b2, const float* b3,
                        const float* c0, const float* c1_, const float* c2, const float* c3) {
    int e = blockIdx.x * blockDim.x + threadIdx.x;
    if (e < NEDGE) {
        int pos = atomicAdd(&g_wofs[g_dst[e]], 1);
        g_eidx[pos] = e;
    }
    if (e < NW1) {
        int w = e >> 11, j = e & 2047;
        g_bc1[e] = (w == 0 ? b0 : w == 1 ? b1 : w == 2 ? b2 : b3)[j];
    }
    if (e < NW2) {
        int w = e >> 6, j = e & 63;
        g_bc2[e] = (w == 0 ? c0 : w == 1 ? c1_ : w == 2 ? c2 : c3)[j];
    }
}

// ===== launch 4: PE add -> fp16 A1 =====
__global__ void k_pe(const float* __restrict__ x, const float* __restrict__ npe,
                     const float* __restrict__ lpe, const float* __restrict__ gpe) {
    int node = blockIdx.x;
    __half* a1 = g_a1 + (size_t)node * INDIM;
    if (node >= NN) {
        for (int j = threadIdx.x; j < INDIM / 2; j += blockDim.x)
            ((uint32_t*)a1)[j] = 0u;
        return;
    }
    int lobe = g_conn[node] - 1;
    int lung = (lobe <= 1) ? 0 : 1;
    const float4* xp = (const float4*)(x + (size_t)node * INDIM);
    const float4* np = (const float4*)(npe + (size_t)(node % NODESP) * INDIM);
    const float4* lp = (const float4*)(lpe + (size_t)lobe * INDIM);
    const float4* gp = (const float4*)(gpe + (size_t)lung * INDIM);
    for (int j = threadIdx.x; j < INDIM / 4; j += blockDim.x) {
        float4 a = xp[j], b = np[j], c = lp[j], d = gp[j];
        float v[4] = { a.x + b.x + c.x + d.x, a.y + b.y + c.y + d.y,
                       a.z + b.z + c.z + d.z, a.w + b.w + c.w + d.w };
        ((__half2*)a1)[2 * j]     = __halves2half2(__float2half_rn(v[0]), __float2half_rn(v[1]));
        ((__half2*)a1)[2 * j + 1] = __halves2half2(__float2half_rn(v[2]), __float2half_rn(v[3]));
    }
}

// ===== launch 5: fused weight transpose -> fp16 (all 8 matrices) =====
__global__ void k_wsplit_all(const float* Wq1, const float* Wk1, const float* Wv1, const float* Ws1,
                             const float* Wq2, const float* Wk2, const float* Wv2, const float* Ws2) {
    __shared__ float tile[32][33];
    int z = blockIdx.z;
    const float* W;
    __half* T;
    int Nw, K, n0, noff;
    if (z < 4) {
        W = (z == 0) ? Wq1 : (z == 1) ? Wk1 : (z == 2) ? Wv1 : Ws1;
        T = g_w1t; Nw = C1; K = INDIM;
        n0 = blockIdx.x * 32; noff = z * 2048;
    } else {
        if (blockIdx.x >= 8) return;
        int mat = blockIdx.x >> 1;
        W = (mat == 0) ? Wq2 : (mat == 1) ? Wk2 : (mat == 2) ? Wv2 : Ws2;
        T = g_w2t; Nw = H2; K = C1;
        n0 = (blockIdx.x & 1) * 32; noff = mat * 64;
    }
    int k0 = blockIdx.y * 32;
    int tx = threadIdx.x, ty = threadIdx.y;  // 32 x 8
#pragma unroll
    for (int r = 0; r < 4; r++)
        tile[ty + r * 8][tx] = W[(size_t)(k0 + ty + r * 8) * Nw + n0 + tx];
    __syncthreads();
#pragma unroll
    for (int r = 0; r < 4; r++) {
        int n = n0 + ty + r * 8;
        T[(size_t)(noff + n) * K + k0 + tx] = __float2half_rn(tile[tx][ty + r * 8]);
    }
}

// ======================= mma.sync fp16 GEMM (single term) =======================
// C[m][n] = sum_k A[m][k]*B[n][k] + bias[n], K=2048.
// BM=128, BN=128, BK=64. 8 warps in 2(M)x4(N); warp tile 64x32.
// Stage row = 128B = 64 fp16 (full BK), XOR-chunk swizzled; A stage 16KB, B stage 16KB.
#define ASTAGE 16384
#define STAGE  32768
#define GSMEM  (3 * STAGE)
#define NCHUNK (KTOT / 64)

__device__ __forceinline__ uint32_t swz(int row, int ch) {
    return (uint32_t)(row * 128 + ((ch ^ (row & 7)) << 4));
}

__device__ __forceinline__ void load_stage(uint32_t sbase, int tid, int s, int c,
        const __half* __restrict__ A, const __half* __restrict__ B, int m0, int n0) {
    uint32_t sa = sbase + s * STAGE;
    uint32_t sb = sa + ASTAGE;
    int k0 = c * 64;
#pragma unroll
    for (int i = 0; i < 4; i++) {
        int idx = tid + i * 256;          // 1024 ops: A rows 0..127, chunks 0..7
        int r = idx >> 3, ch = idx & 7;
        cpa16(sa + swz(r, ch), A + (size_t)(m0 + r) * KTOT + k0 + ch * 8);
    }
#pragma unroll
    for (int i = 0; i < 4; i++) {
        int idx = tid + i * 256;          // 1024 ops: B rows 0..127, chunks 0..7
        int r = idx >> 3, ch = idx & 7;
        cpa16(sb + swz(r, ch), B + (size_t)(n0 + r) * KTOT + k0 + ch * 8);
    }
    cpa_commit();
}

__global__ void __launch_bounds__(256, 1) mm_gemm(
        const __half* __restrict__ A, const __half* __restrict__ B,
        const float* __restrict__ bias, float* __restrict__ C, int ldc) {
    extern __shared__ char smem[];
    uint32_t sbase = smem_u32(smem);
    int tid = threadIdx.x, lane = tid & 31, wid = tid >> 5;
    int wm = wid >> 2, wn = wid & 3;
    int m0 = blockIdx.y * 128, n0 = blockIdx.x * 128;

    float acc[4][4][4];
#pragma unroll
    for (int i = 0; i < 4; i++)
#pragma unroll
        for (int j = 0; j < 4; j++)
#pragma unroll
            for (int q = 0; q < 4; q++) acc[i][j][q] = 0.f;

    load_stage(sbase, tid, 0, 0, A, B, m0, n0);
    load_stage(sbase, tid, 1, 1, A, B, m0, n0);
    load_stage(sbase, tid, 2, 2, A, B, m0, n0);

    int a_row_l = (lane & 15);
    int a_chl   = (lane >> 4);
    int b_row_l = (lane & 7) + ((lane >> 4) << 3);
    int b_chl   = ((lane >> 3) & 1);

    for (int c = 0; c < NCHUNK; c++) {
        cpa_wait2();
        __syncthreads();
        uint32_t sa = sbase + (c % 3) * STAGE;
        uint32_t sb = sa + ASTAGE;
#pragma unroll
        for (int ks = 0; ks < 4; ks++) {
            uint32_t a_f[4][4], b_f[2][4];
#pragma unroll
            for (int mt = 0; mt < 4; mt++) {
                int row = wm * 64 + mt * 16 + a_row_l;
                ldsm4(a_f[mt], sa + swz(row, ks * 2 + a_chl));
            }
#pragma unroll
            for (int np = 0; np < 2; np++) {
                int row = wn * 32 + np * 16 + b_row_l;
                ldsm4(b_f[np], sb + swz(row, ks * 2 + b_chl));
            }
#pragma unroll
            for (int mt = 0; mt < 4; mt++)
#pragma unroll
                for (int nt = 0; nt < 4; nt++)
                    mma16816(acc[mt][nt], a_f[mt], &b_f[nt >> 1][(nt & 1) * 2]);
        }
        __syncthreads();
        if (c + 3 < NCHUNK)
            load_stage(sbase, tid, (c + 3) % 3, c + 3, A, B, m0, n0);
        else
            cpa_commit();
    }

#pragma unroll
    for (int mt = 0; mt < 4; mt++) {
        int row = m0 + wm * 64 + mt * 16 + (lane >> 2);
#pragma unroll
        for (int nt = 0; nt < 4; nt++) {
            int col = n0 + wn * 32 + nt * 8 + (lane & 3) * 2;
            float b0 = bias[col], b1 = bias[col + 1];
            float* p0 = C + (size_t)row * ldc + col;
            p0[0] = acc[mt][nt][0] + b0;
            p0[1] = acc[mt][nt][1] + b1;
            float* p1 = p0 + 8 * ldc;
            p1[0] = acc[mt][nt][2] + b0;
            p1[1] = acc[mt][nt][3] + b1;
        }
    }
}

// ======================= fused conv1 attention (CSR, no atomics) =======================
// g_c1 per-node (stride 8192): q[0:2048] k[2048:4096] v[4096:6144] s[6144:8192]
__global__ void __launch_bounds__(256) k_att1() {
    __shared__ float s_part[32][8];
    __shared__ float s_den[2];
    int node = blockIdx.x;
    int tid = threadIdx.x, lane = tid & 31, wid = tid >> 5;
    int tcol = tid * 8;
    int head = tid >> 7;
    int ofs = g_ofs[node], nE = g_ofs[node + 1] - ofs;

    if (tid < 2) s_den[tid] = 0.f;

    float qreg[8];
    const float4* qp = (const float4*)(g_c1 + (size_t)node * NW1 + tcol);
    *(float4*)&qreg[0] = qp[0];
    *(float4*)&qreg[4] = qp[1];
    __syncthreads();

    for (int t0 = 0; t0 < nE; t0 += 32) {
        int tE = min(32, nE - t0);
        for (int e = 0; e < tE; e++) {
            int eid = g_eidx[ofs + t0 + e];
            int src = g_src[eid];
            const float4* kp = (const float4*)(g_c1 + (size_t)src * NW1 + 2048 + tcol);
            float4 k0 = kp[0], k1 = kp[1];
            float p = qreg[0] * k0.x + qreg[1] * k0.y + qreg[2] * k0.z + qreg[3] * k0.w
                    + qreg[4] * k1.x + qreg[5] * k1.y + qreg[6] * k1.z + qreg[7] * k1.w;
#pragma unroll
            for (int off = 16; off; off >>= 1) p += __shfl_xor_sync(0xffffffffu, p, off);
            if (lane == 0) s_part[e][wid] = p;
        }
        __syncthreads();
        if (tid < tE * 2) {
            int e = tid >> 1, h = tid & 1;
            float d = s_part[e][h * 4 + 0] + s_part[e][h * 4 + 1]
                    + s_part[e][h * 4 + 2] + s_part[e][h * 4 + 3];
            float ex = expf(d * (1.f / 32.f));   // softmax shift-invariant, alpha O(1)
            int eid = g_eidx[ofs + t0 + e];
            g_al1[eid * 2 + h] = ex;
            atomicAdd(&s_den[h], ex);
        }
        __syncthreads();
    }

    float invd = 1.f / (s_den[head] + 1e-16f);

    float acc[8] = {0.f, 0.f, 0.f, 0.f, 0.f, 0.f, 0.f, 0.f};
    for (int i = 0; i < nE; i++) {
        int eid = g_eidx[ofs + i];
        int src = g_src[eid];
        float a = g_al1[eid * 2 + head] * invd;
        const float4* vp = (const float4*)(g_c1 + (size_t)src * NW1 + 4096 + tcol);
        float4 v0 = vp[0], v1 = vp[1];
        acc[0] += a * v0.x; acc[1] += a * v0.y; acc[2] += a * v0.z; acc[3] += a * v0.w;
        acc[4] += a * v1.x; acc[5] += a * v1.y; acc[6] += a * v1.z; acc[7] += a * v1.w;
    }

    const float4* sp = (const float4*)(g_c1 + (size_t)node * NW1 + 6144 + tcol);
    float4 s0 = sp[0], s1 = sp[1];
    float skip[8] = {s0.x, s0.y, s0.z, s0.w, s1.x, s1.y, s1.z, s1.w};
    union { __half b[8]; uint4 u; } H;
#pragma unroll
    for (int j = 0; j < 8; j++)
        H.b[j] = __float2half_rn(fmaxf(acc[j] + skip[j], 0.f));
    *(uint4*)(g_a2 + (size_t)node * C1 + tcol) = H.u;
}

// ======================= fused conv2 attention (CSR, no atomics) =======================
__global__ void __launch_bounds__(64) k_att2() {
    __shared__ float s_part[32][2];
    __shared__ float s_den;
    int node = blockIdx.x;
    int tid = threadIdx.x, lane = tid & 31, wid = tid >> 5;
    int ofs = g_ofs[node], nE = g_ofs[node + 1] - ofs;

    if (tid == 0) s_den = 0.f;
    float qreg = g_c2[(size_t)node * NW2 + tid];
    __syncthreads();

    for (int t0 = 0; t0 < nE; t0 += 32) {
        int tE = min(32, nE - t0);
        for (int e = 0; e < tE; e++) {
            int eid = g_eidx[ofs + t0 + e];
            int src = g_src[eid];
            float p = qreg * g_c2[(size_t)src * NW2 + 64 + tid];
#pragma unroll
            for (int off = 16; off; off >>= 1) p += __shfl_xor_sync(0xffffffffu, p, off);
            if (lane == 0) s_part[e][wid] = p;
        }
        __syncthreads();
        if (tid < tE) {
            float d = s_part[tid][0] + s_part[tid][1];
            float ex = expf(d * 0.125f);
            g_al2[g_eidx[ofs + t0 + tid]] = ex;
            atomicAdd(&s_den, ex);
        }
        __syncthreads();
    }

    float invd = 1.f / (s_den + 1e-16f);
    float acc = 0.f;
    for (int i = 0; i < nE; i++) {
        int eid = g_eidx[ofs + i];
        int src = g_src[eid];
        acc += g_al2[eid] * invd * g_c2[(size_t)src * NW2 + 128 + tid];
    }
    float skip = g_c2[(size_t)node * NW2 + 192 + tid];
    g_out2[(size_t)node * H2 + tid] = fmaxf(acc + skip, 0.f);
}

// ======================= FC head =======================
__global__ void fc1s(const float* __restrict__ W, const float* __restrict__ b) {
    int g = blockIdx.x, ks = blockIdx.y, n = threadIdx.x;
    const float* a = g_out2 + (size_t)g * FCK + ks * 1920;
    const float* w = W + (size_t)ks * 1920 * 256 + n;
    float s0 = (ks == 0) ? b[n] : 0.f, s1 = 0.f, s2 = 0.f, s3 = 0.f;
    for (int k = 0; k < 1920; k += 4) {
        s0 = fmaf(a[k + 0], w[(size_t)(k + 0) * 256], s0);
        s1 = fmaf(a[k + 1], w[(size_t)(k + 1) * 256], s1);
        s2 = fmaf(a[k + 2], w[(size_t)(k + 2) * 256], s2);
        s3 = fmaf(a[k + 3], w[(size_t)(k + 3) * 256], s3);
    }
    atomicAdd(&g_f1[g * 256 + n], (s0 + s1) + (s2 + s3));
}

__global__ void fc(const float* __restrict__ A, const float* __restrict__ W,
                   const float* __restrict__ b, float* __restrict__ C,
                   int N, int K, int relu_out, int relu_in) {
    int m = blockIdx.x, n = threadIdx.x;
    if (n >= N) return;
    const float* a = A + (size_t)m * K;
    float s = b[n];
    for (int k = 0; k < K; k++) {
        float av = a[k];
        if (relu_in) av = fmaxf(av, 0.f);
        s = fmaf(av, W[(size_t)k * N + n], s);
    }
    if (relu_out) s = fmaxf(s, 0.f);
    C[(size_t)m * N + n] = s;
}

// ======================= launch =======================
extern "C" void kernel_launch(void* const* d_in, const int* in_sizes, int n_in,
                              void* d_out, int out_size) {
    const float* x = (const float*)d_in[0];
    const int* ei = (const int*)d_in[1];
    const int* conn = (const int*)d_in[2];
    const float* npe = (const float*)d_in[3];
    const float* lpe = (const float*)d_in[4];
    const float* gpe = (const float*)d_in[5];
    const float* Wq1 = (const float*)d_in[6];  const float* bq1 = (const float*)d_in[7];
    const float* Wk1 = (const float*)d_in[8];  const float* bk1 = (const float*)d_in[9];
    const float* Wv1 = (const float*)d_in[10]; const float* bv1 = (const float*)d_in[11];
    const float* Ws1 = (const float*)d_in[12]; const float* bs1 = (const float*)d_in[13];
    const float* Wq2 = (const float*)d_in[14]; const float* bq2 = (const float*)d_in[15];
    const float* Wk2 = (const float*)d_in[16]; const float* bk2 = (const float*)d_in[17];
    const float* Wv2 = (const float*)d_in[18]; const float* bv2 = (const float*)d_in[19];
    const float* Ws2 = (const float*)d_in[20]; const float* bs2 = (const float*)d_in[21];
    const float* Wf1 = (const float*)d_in[22]; const float* bf1 = (const float*)d_in[23];
    const float* Wf2 = (const float*)d_in[24]; const float* bf2 = (const float*)d_in[25];
    const float* Wf3 = (const float*)d_in[26]; const float* bf3 = (const float*)d_in[27];
    const float* Wf4 = (const float*)d_in[28]; const float* bf4 = (const float*)d_in[29];

    cudaFuncSetAttribute(mm_gemm, cudaFuncAttributeMaxDynamicSharedMemorySize, GSMEM);

    float *c1p, *c2p, *f1p, *f2p, *f3p, *bc1p, *bc2p;
    __half *a1p, *a2p, *w1tp, *w2tp;
    cudaGetSymbolAddress((void**)&c1p, g_c1);
    cudaGetSymbolAddress((void**)&c2p, g_c2);
    cudaGetSymbolAddress((void**)&f1p, g_f1);
    cudaGetSymbolAddress((void**)&f2p, g_f2);
    cudaGetSymbolAddress((void**)&f3p, g_f3);
    cudaGetSymbolAddress((void**)&bc1p, g_bc1);
    cudaGetSymbolAddress((void**)&bc2p, g_bc2);
    cudaGetSymbolAddress((void**)&a1p, g_a1);
    cudaGetSymbolAddress((void**)&a2p, g_a2);
    cudaGetSymbolAddress((void**)&w1tp, g_w1t);
    cudaGetSymbolAddress((void**)&w2tp, g_w2t);

    k_cvt<<<256, 256>>>(ei, conn);
    k_scan<<<1, 1024>>>();
    k_fillb<<<(NEDGE + 255) / 256, 256>>>(bq1, bk1, bv1, bs1, bq2, bk2, bv2, bs2);
    k_pe<<<NP, 256>>>(x, npe, lpe, gpe);
    k_wsplit_all<<<dim3(64, 64, 5), dim3(32, 8)>>>(Wq1, Wk1, Wv1, Ws1, Wq2, Wk2, Wv2, Ws2);

    // conv1: fused 4-weight GEMM  [NP,2048] x [2048,8192]
    mm_gemm<<<dim3(NW1 / 128, NP / 128), 256, GSMEM>>>(a1p, w1tp, bc1p, c1p, NW1);

    k_att1<<<NN, 256>>>();

    // conv2: fused 4-weight GEMM  [NP,2048] x [2048,256]
    mm_gemm<<<dim3(NW2 / 128, NP / 128), 256, GSMEM>>>(a2p, w2tp, bc2p, c2p, NW2);

    k_att2<<<NN, 64>>>();

    fc1s<<<dim3(NGRAPH, 14), 256>>>(Wf1, bf1);
    fc<<<NGRAPH, 128>>>(f1p, Wf2, bf2, f2p, 128, 256, 1, 1);
    fc<<<NGRAPH, 64>>>(f2p, Wf3, bf3, f3p, 64, 128, 1, 0);
    fc<<<NGRAPH, 32>>>(f3p, Wf4, bf4, (float*)d_out, OUTD, 64, 0, 0);
}

// round 14
// speedup vs baseline: 10.6583x; 1.1728x over previous
#include <cuda_runtime.h>
#include <cuda_fp16.h>
#include <cstdint>

#define NGRAPH 16
#define NODESP 420
#define NN     6720
#define NP     6784    // padded to 53*128
#define NEDGE  53760
#define INDIM  2048
#define C1     2048
#define H1     1024
#define H2     64
#define OUTD   18
#define FCK    26880
#define NW1    8192    // 4 fused conv1 weight mats
#define NW2    256     // 4 fused conv2 weight mats
#define KTOT   2048

// ======================= device scratch =======================
__device__ float  g_q1f[(size_t)NP * 2048];   // conv1 q (fp32)
__device__ float  g_s1f[(size_t)NP * 2048];   // conv1 skip (fp32)
__device__ __half g_kv1h[(size_t)NP * 4096];  // conv1 k|v (fp16)
__device__ float g_al1[NEDGE * 2];            // per-edge exp (spill)
__device__ float g_c2[(size_t)NP * NW2];      // fused q|k|v|s conv2 out
__device__ float g_out2[(size_t)NN * H2];
__device__ float g_al2[NEDGE];
__device__ float g_f1[NGRAPH * 256];
__device__ float g_f2[NGRAPH * 128];
__device__ float g_f3[NGRAPH * 64];
__device__ int   g_src[NEDGE];
__device__ int   g_dst[NEDGE];
__device__ int   g_conn[NN];
__device__ int   g_ofs[NN + 1];
__device__ int   g_wofs[NN];
__device__ int   g_eidx[NEDGE];
__device__ __half g_a1[(size_t)NP * INDIM];   // A1 fp16
__device__ __half g_a2[(size_t)NP * C1];      // A2 fp16
__device__ __half g_w1t[(size_t)NW1 * INDIM]; // W1^T fp16 [n][k]
__device__ __half g_w2t[(size_t)NW2 * C1];
__device__ float g_bc1[NW1];
__device__ float g_bc2[NW2];

// ======================= sm_80-baseline PTX wrappers =======================
__device__ __forceinline__ uint32_t smem_u32(const void* p) {
    uint32_t a;
    asm("{ .reg .u64 t; cvta.to.shared.u64 t, %1; cvt.u32.u64 %0, t; }" : "=r"(a) : "l"(p));
    return a;
}
__device__ __forceinline__ void cpa16(uint32_t s, const void* g) {
    asm volatile("cp.async.cg.shared.global [%0], [%1], 16;" :: "r"(s), "l"(g));
}
__device__ __forceinline__ void cpa_commit() {
    asm volatile("cp.async.commit_group;" ::: "memory");
}
__device__ __forceinline__ void cpa_wait2() {
    asm volatile("cp.async.wait_group 2;" ::: "memory");
}
__device__ __forceinline__ void ldsm4(uint32_t* r, uint32_t addr) {
    asm volatile("ldmatrix.sync.aligned.m8n8.x4.shared.b16 {%0,%1,%2,%3}, [%4];"
        : "=r"(r[0]), "=r"(r[1]), "=r"(r[2]), "=r"(r[3]) : "r"(addr));
}
__device__ __forceinline__ void mma16816(float* d, const uint32_t* a, const uint32_t* b) {
    asm volatile("mma.sync.aligned.m16n8k16.row.col.f32.f16.f16.f32 "
        "{%0,%1,%2,%3}, {%4,%5,%6,%7}, {%8,%9}, {%0,%1,%2,%3};"
        : "+f"(d[0]), "+f"(d[1]), "+f"(d[2]), "+f"(d[3])
        : "r"(a[0]), "r"(a[1]), "r"(a[2]), "r"(a[3]), "r"(b[0]), "r"(b[1]));
}

// ===== launch 1: index normalization + init (g_f1 seeded with bias) =====
__global__ void k_cvt(const int* __restrict__ ei, const int* __restrict__ conn,
                      const float* __restrict__ bf1) {
    bool is64 = true;
#pragma unroll
    for (int i = 0; i < 16; i++)
        if (ei[2 * i + 1] != 0) is64 = false;
    int t = blockIdx.x * blockDim.x + threadIdx.x;
    int stride = gridDim.x * blockDim.x;
    if (is64) {
        for (int i = t; i < NEDGE; i += stride) { g_src[i] = ei[2 * i]; g_dst[i] = ei[2 * (NEDGE + i)]; }
        for (int i = t; i < NN; i += stride) g_conn[i] = conn[2 * i];
    } else {
        for (int i = t; i < NEDGE; i += stride) { g_src[i] = ei[i]; g_dst[i] = ei[NEDGE + i]; }
        for (int i = t; i < NN; i += stride) g_conn[i] = conn[i];
    }
    for (int i = t; i < NGRAPH * 256; i += stride) g_f1[i] = bf1[i & 255];
    // pad rows NN..NP of conv2 input must stay zero
    const __half z = __float2half(0.f);
    for (size_t j = (size_t)NN * C1 + t; j < (size_t)NP * C1; j += stride)
        g_a2[j] = z;
}

// ===== launch 2: smem histogram + scan -> CSR offsets =====
__global__ void k_scan() {
    __shared__ int scnt[NN];
    __shared__ int sh[1024];
    int t = threadIdx.x;
    for (int i = t; i < NN; i += 1024) scnt[i] = 0;
    __syncthreads();
    for (int e = t; e < NEDGE; e += 1024) atomicAdd(&scnt[g_dst[e]], 1);
    __syncthreads();
    int base = t * 7;
    int loc[7];
    int s = 0;
#pragma unroll
    for (int i = 0; i < 7; i++) {
        int n = base + i;
        int c = (n < NN) ? scnt[n] : 0;
        loc[i] = s;
        s += c;
    }
    sh[t] = s;
    __syncthreads();
    for (int off = 1; off < 1024; off <<= 1) {
        int v = (t >= off) ? sh[t - off] : 0;
        __syncthreads();
        sh[t] += v;
        __syncthreads();
    }
    int ex0 = sh[t] - s;
#pragma unroll
    for (int i = 0; i < 7; i++) {
        int n = base + i;
        if (n < NN) {
            g_ofs[n] = ex0 + loc[i];
            g_wofs[n] = ex0 + loc[i];
        }
    }
    if (t == 0) g_ofs[NN] = NEDGE;
}

// ===== launch 3: CSR fill + fused bias packing =====
__global__ void k_fillb(const float* b0, const float* b1, const float* b2, const float* b3,
                        const float* c0, const float* c1_, const float* c2, const float* c3) {
    int e = blockIdx.x * blockDim.x + threadIdx.x;
    if (e < NEDGE) {
        int pos = atomicAdd(&g_wofs[g_dst[e]], 1);
        g_eidx[pos] = e;
    }
    if (e < NW1) {
        int w = e >> 11, j = e & 2047;
        g_bc1[e] = (w == 0 ? b0 : w == 1 ? b1 : w == 2 ? b2 : b3)[j];
    }
    if (e < NW2) {
        int w = e >> 6, j = e & 63;
        g_bc2[e] = (w == 0 ? c0 : w == 1 ? c1_ : w == 2 ? c2 : c3)[j];
    }
}

// ===== launch 4: PE add -> fp16 A1 =====
__global__ void k_pe(const float* __restrict__ x, const float* __restrict__ npe,
                     const float* __restrict__ lpe, const float* __restrict__ gpe) {
    int node = blockIdx.x;
    __half* a1 = g_a1 + (size_t)node * INDIM;
    if (node >= NN) {
        for (int j = threadIdx.x; j < INDIM / 2; j += blockDim.x)
            ((uint32_t*)a1)[j] = 0u;
        return;
    }
    int lobe = g_conn[node] - 1;
    int lung = (lobe <= 1) ? 0 : 1;
    const float4* xp = (const float4*)(x + (size_t)node * INDIM);
    const float4* np = (const float4*)(npe + (size_t)(node % NODESP) * INDIM);
    const float4* lp = (const float4*)(lpe + (size_t)lobe * INDIM);
    const float4* gp = (const float4*)(gpe + (size_t)lung * INDIM);
    for (int j = threadIdx.x; j < INDIM / 4; j += blockDim.x) {
        float4 a = xp[j], b = np[j], c = lp[j], d = gp[j];
        float v[4] = { a.x + b.x + c.x + d.x, a.y + b.y + c.y + d.y,
                       a.z + b.z + c.z + d.z, a.w + b.w + c.w + d.w };
        ((__half2*)a1)[2 * j]     = __halves2half2(__float2half_rn(v[0]), __float2half_rn(v[1]));
        ((__half2*)a1)[2 * j + 1] = __halves2half2(__float2half_rn(v[2]), __float2half_rn(v[3]));
    }
}

// ===== launch 5: fused weight transpose -> fp16 (all 8 matrices) =====
__global__ void k_wsplit_all(const float* Wq1, const float* Wk1, const float* Wv1, const float* Ws1,
                             const float* Wq2, const float* Wk2, const float* Wv2, const float* Ws2) {
    __shared__ float tile[32][33];
    int z = blockIdx.z;
    const float* W;
    __half* T;
    int Nw, K, n0, noff;
    if (z < 4) {
        W = (z == 0) ? Wq1 : (z == 1) ? Wk1 : (z == 2) ? Wv1 : Ws1;
        T = g_w1t; Nw = C1; K = INDIM;
        n0 = blockIdx.x * 32; noff = z * 2048;
    } else {
        if (blockIdx.x >= 8) return;
        int mat = blockIdx.x >> 1;
        W = (mat == 0) ? Wq2 : (mat == 1) ? Wk2 : (mat == 2) ? Wv2 : Ws2;
        T = g_w2t; Nw = H2; K = C1;
        n0 = (blockIdx.x & 1) * 32; noff = mat * 64;
    }
    int k0 = blockIdx.y * 32;
    int tx = threadIdx.x, ty = threadIdx.y;  // 32 x 8
#pragma unroll
    for (int r = 0; r < 4; r++)
        tile[ty + r * 8][tx] = W[(size_t)(k0 + ty + r * 8) * Nw + n0 + tx];
    __syncthreads();
#pragma unroll
    for (int r = 0; r < 4; r++) {
        int n = n0 + ty + r * 8;
        T[(size_t)(noff + n) * K + k0 + tx] = __float2half_rn(tile[tx][ty + r * 8]);
    }
}

// ======================= mma.sync fp16 GEMM (single term) =======================
// mode 0: C[m][n] = sum + bias[n] (fp32, ldc)
// mode 1: conv1 layout: cols [0,2048)->g_q1f fp32, [2048,6144)->g_kv1h fp16, [6144,8192)->g_s1f fp32
#define ASTAGE 16384
#define STAGE  32768
#define GSMEM  (3 * STAGE)
#define NCHUNK (KTOT / 64)

__device__ __forceinline__ uint32_t swz(int row, int ch) {
    return (uint32_t)(row * 128 + ((ch ^ (row & 7)) << 4));
}

__device__ __forceinline__ void load_stage(uint32_t sbase, int tid, int s, int c,
        const __half* __restrict__ A, const __half* __restrict__ B, int m0, int n0) {
    uint32_t sa = sbase + s * STAGE;
    uint32_t sb = sa + ASTAGE;
    int k0 = c * 64;
#pragma unroll
    for (int i = 0; i < 4; i++) {
        int idx = tid + i * 256;
        int r = idx >> 3, ch = idx & 7;
        cpa16(sa + swz(r, ch), A + (size_t)(m0 + r) * KTOT + k0 + ch * 8);
    }
#pragma unroll
    for (int i = 0; i < 4; i++) {
        int idx = tid + i * 256;
        int r = idx >> 3, ch = idx & 7;
        cpa16(sb + swz(r, ch), B + (size_t)(n0 + r) * KTOT + k0 + ch * 8);
    }
    cpa_commit();
}

__global__ void __launch_bounds__(256, 1) mm_gemm(
        const __half* __restrict__ A, const __half* __restrict__ B,
        const float* __restrict__ bias, float* __restrict__ C, int ldc, int mode) {
    extern __shared__ char smem[];
    uint32_t sbase = smem_u32(smem);
    int tid = threadIdx.x, lane = tid & 31, wid = tid >> 5;
    int wm = wid >> 2, wn = wid & 3;
    int m0 = blockIdx.y * 128, n0 = blockIdx.x * 128;

    float acc[4][4][4];
#pragma unroll
    for (int i = 0; i < 4; i++)
#pragma unroll
        for (int j = 0; j < 4; j++)
#pragma unroll
            for (int q = 0; q < 4; q++) acc[i][j][q] = 0.f;

    load_stage(sbase, tid, 0, 0, A, B, m0, n0);
    load_stage(sbase, tid, 1, 1, A, B, m0, n0);
    load_stage(sbase, tid, 2, 2, A, B, m0, n0);

    int a_row_l = (lane & 15);
    int a_chl   = (lane >> 4);
    int b_row_l = (lane & 7) + ((lane >> 4) << 3);
    int b_chl   = ((lane >> 3) & 1);

    for (int c = 0; c < NCHUNK; c++) {
        cpa_wait2();
        __syncthreads();
        uint32_t sa = sbase + (c % 3) * STAGE;
        uint32_t sb = sa + ASTAGE;
#pragma unroll
        for (int ks = 0; ks < 4; ks++) {
            uint32_t a_f[4][4], b_f[2][4];
#pragma unroll
            for (int mt = 0; mt < 4; mt++) {
                int row = wm * 64 + mt * 16 + a_row_l;
                ldsm4(a_f[mt], sa + swz(row, ks * 2 + a_chl));
            }
#pragma unroll
            for (int np = 0; np < 2; np++) {
                int row = wn * 32 + np * 16 + b_row_l;
                ldsm4(b_f[np], sb + swz(row, ks * 2 + b_chl));
            }
#pragma unroll
            for (int mt = 0; mt < 4; mt++)
#pragma unroll
                for (int nt = 0; nt < 4; nt++)
                    mma16816(acc[mt][nt], a_f[mt], &b_f[nt >> 1][(nt & 1) * 2]);
        }
        __syncthreads();
        if (c + 3 < NCHUNK)
            load_stage(sbase, tid, (c + 3) % 3, c + 3, A, B, m0, n0);
        else
            cpa_commit();
    }

#pragma unroll
    for (int mt = 0; mt < 4; mt++) {
        int row = m0 + wm * 64 + mt * 16 + (lane >> 2);
#pragma unroll
        for (int nt = 0; nt < 4; nt++) {
            int cg = n0 + wn * 32 + nt * 8 + (lane & 3) * 2;
            float b0 = bias[cg], b1 = bias[cg + 1];
            float v00 = acc[mt][nt][0] + b0, v01 = acc[mt][nt][1] + b1;
            float v10 = acc[mt][nt][2] + b0, v11 = acc[mt][nt][3] + b1;
            if (mode == 0) {
                float* p0 = C + (size_t)row * ldc + cg;
                p0[0] = v00; p0[1] = v01;
                float* p1 = p0 + 8 * ldc;
                p1[0] = v10; p1[1] = v11;
            } else if (cg < 2048) {
                float* p0 = g_q1f + (size_t)row * 2048 + cg;
                p0[0] = v00; p0[1] = v01;
                p0 += 8 * 2048;
                p0[0] = v10; p0[1] = v11;
            } else if (cg < 6144) {
                __half* p0 = g_kv1h + (size_t)row * 4096 + (cg - 2048);
                *(__half2*)p0 = __floats2half2_rn(v00, v01);
                *(__half2*)(p0 + 8 * 4096) = __floats2half2_rn(v10, v11);
            } else {
                float* p0 = g_s1f + (size_t)row * 2048 + (cg - 6144);
                p0[0] = v00; p0[1] = v01;
                p0 += 8 * 2048;
                p0[0] = v10; p0[1] = v11;
            }
        }
    }
}

// ======================= fused conv1 attention (CSR, no atomics) =======================
// q: g_q1f [node][2048] fp32; k|v: g_kv1h [node][4096] fp16 (k 0..2047, v 2048..4095);
// skip: g_s1f [node][2048] fp32. Thread t owns cols t*8..t*8+7 (head = t>>7).
__global__ void __launch_bounds__(256) k_att1() {
    __shared__ float s_part[32][8];
    __shared__ float s_den[2];
    int node = blockIdx.x;
    int tid = threadIdx.x, lane = tid & 31, wid = tid >> 5;
    int tcol = tid * 8;
    int head = tid >> 7;
    int ofs = g_ofs[node], nE = g_ofs[node + 1] - ofs;

    if (tid < 2) s_den[tid] = 0.f;

    float qreg[8];
    const float4* qp = (const float4*)(g_q1f + (size_t)node * 2048 + tcol);
    *(float4*)&qreg[0] = qp[0];
    *(float4*)&qreg[4] = qp[1];
    __syncthreads();

    for (int t0 = 0; t0 < nE; t0 += 32) {
        int tE = min(32, nE - t0);
        for (int e = 0; e < tE; e++) {
            int eid = g_eidx[ofs + t0 + e];
            int src = g_src[eid];
            union { uint4 u; __half2 h[4]; } K;
            K.u = *(const uint4*)(g_kv1h + (size_t)src * 4096 + tcol);
            float2 k0 = __half22float2(K.h[0]), k1 = __half22float2(K.h[1]);
            float2 k2 = __half22float2(K.h[2]), k3 = __half22float2(K.h[3]);
            float p = qreg[0] * k0.x + qreg[1] * k0.y + qreg[2] * k1.x + qreg[3] * k1.y
                    + qreg[4] * k2.x + qreg[5] * k2.y + qreg[6] * k3.x + qreg[7] * k3.y;
#pragma unroll
            for (int off = 16; off; off >>= 1) p += __shfl_xor_sync(0xffffffffu, p, off);
            if (lane == 0) s_part[e][wid] = p;
        }
        __syncthreads();
        if (tid < tE * 2) {
            int e = tid >> 1, h = tid & 1;
            float d = s_part[e][h * 4 + 0] + s_part[e][h * 4 + 1]
                    + s_part[e][h * 4 + 2] + s_part[e][h * 4 + 3];
            float ex = expf(d * (1.f / 32.f));   // softmax shift-invariant, alpha O(1)
            int eid = g_eidx[ofs + t0 + e];
            g_al1[eid * 2 + h] = ex;
            atomicAdd(&s_den[h], ex);
        }
        __syncthreads();
    }

    float invd = 1.f / (s_den[head] + 1e-16f);

    float acc[8] = {0.f, 0.f, 0.f, 0.f, 0.f, 0.f, 0.f, 0.f};
    for (int i = 0; i < nE; i++) {
        int eid = g_eidx[ofs + i];
        int src = g_src[eid];
        float a = g_al1[eid * 2 + head] * invd;
        union { uint4 u; __half2 h[4]; } V;
        V.u = *(const uint4*)(g_kv1h + (size_t)src * 4096 + 2048 + tcol);
        float2 v0 = __half22float2(V.h[0]), v1 = __half22float2(V.h[1]);
        float2 v2 = __half22float2(V.h[2]), v3 = __half22float2(V.h[3]);
        acc[0] += a * v0.x; acc[1] += a * v0.y; acc[2] += a * v1.x; acc[3] += a * v1.y;
        acc[4] += a * v2.x; acc[5] += a * v2.y; acc[6] += a * v3.x; acc[7] += a * v3.y;
    }

    const float4* sp = (const float4*)(g_s1f + (size_t)node * 2048 + tcol);
    float4 s0 = sp[0], s1 = sp[1];
    float skip[8] = {s0.x, s0.y, s0.z, s0.w, s1.x, s1.y, s1.z, s1.w};
    union { __half b[8]; uint4 u; } H;
#pragma unroll
    for (int j = 0; j < 8; j++)
        H.b[j] = __float2half_rn(fmaxf(acc[j] + skip[j], 0.f));
    *(uint4*)(g_a2 + (size_t)node * C1 + tcol) = H.u;
}

// ======================= fused conv2 attention (CSR, no atomics) =======================
__global__ void __launch_bounds__(64) k_att2() {
    __shared__ float s_part[32][2];
    __shared__ float s_den;
    int node = blockIdx.x;
    int tid = threadIdx.x, lane = tid & 31, wid = tid >> 5;
    int ofs = g_ofs[node], nE = g_ofs[node + 1] - ofs;

    if (tid == 0) s_den = 0.f;
    float qreg = g_c2[(size_t)node * NW2 + tid];
    __syncthreads();

    for (int t0 = 0; t0 < nE; t0 += 32) {
        int tE = min(32, nE - t0);
        for (int e = 0; e < tE; e++) {
            int eid = g_eidx[ofs + t0 + e];
            int src = g_src[eid];
            float p = qreg * g_c2[(size_t)src * NW2 + 64 + tid];
#pragma unroll
            for (int off = 16; off; off >>= 1) p += __shfl_xor_sync(0xffffffffu, p, off);
            if (lane == 0) s_part[e][wid] = p;
        }
        __syncthreads();
        if (tid < tE) {
            float d = s_part[tid][0] + s_part[tid][1];
            float ex = expf(d * 0.125f);
            g_al2[g_eidx[ofs + t0 + tid]] = ex;
            atomicAdd(&s_den, ex);
        }
        __syncthreads();
    }

    float invd = 1.f / (s_den + 1e-16f);
    float acc = 0.f;
    for (int i = 0; i < nE; i++) {
        int eid = g_eidx[ofs + i];
        int src = g_src[eid];
        acc += g_al2[eid] * invd * g_c2[(size_t)src * NW2 + 128 + tid];
    }
    float skip = g_c2[(size_t)node * NW2 + 192 + tid];
    g_out2[(size_t)node * H2 + tid] = fmaxf(acc + skip, 0.f);
}

// ======================= FC head =======================
// fc1: k-sliced, W read ONCE; partials accumulated into bias-seeded g_f1.
#define FSLICE 240
__global__ void __launch_bounds__(256) fc1s(const float* __restrict__ W) {
    __shared__ float a_s[FSLICE][17];   // pad 17 kills 16-way store conflict
    int k0 = blockIdx.x * FSLICE;
    int n = threadIdx.x;
    if (n < FSLICE) {
#pragma unroll
        for (int g = 0; g < NGRAPH; g++)
            a_s[n][g] = g_out2[(size_t)g * FCK + k0 + n];
    }
    __syncthreads();
    float acc[NGRAPH];
#pragma unroll
    for (int g = 0; g < NGRAPH; g++) acc[g] = 0.f;
    for (int k = 0; k < FSLICE; k++) {
        float w = W[(size_t)(k0 + k) * 256 + n];
#pragma unroll
        for (int g = 0; g < NGRAPH; g++)
            acc[g] = fmaf(a_s[k][g], w, acc[g]);
    }
#pragma unroll
    for (int g = 0; g < NGRAPH; g++)
        atomicAdd(&g_f1[g * 256 + n], acc[g]);
}

__global__ void fc(const float* __restrict__ A, const float* __restrict__ W,
                   const float* __restrict__ b, float* __restrict__ C,
                   int N, int K, int relu_out, int relu_in) {
    int m = blockIdx.x, n = threadIdx.x;
    if (n >= N) return;
    const float* a = A + (size_t)m * K;
    float s = b[n];
    for (int k = 0; k < K; k++) {
        float av = a[k];
        if (relu_in) av = fmaxf(av, 0.f);
        s = fmaf(av, W[(size_t)k * N + n], s);
    }
    if (relu_out) s = fmaxf(s, 0.f);
    C[(size_t)m * N + n] = s;
}

// ======================= launch =======================
extern "C" void kernel_launch(void* const* d_in, const int* in_sizes, int n_in,
                              void* d_out, int out_size) {
    const float* x = (const float*)d_in[0];
    const int* ei = (const int*)d_in[1];
    const int* conn = (const int*)d_in[2];
    const float* npe = (const float*)d_in[3];
    const float* lpe = (const float*)d_in[4];
    const float* gpe = (const float*)d_in[5];
    const float* Wq1 = (const float*)d_in[6];  const float* bq1 = (const float*)d_in[7];
    const float* Wk1 = (const float*)d_in[8];  const float* bk1 = (const float*)d_in[9];
    const float* Wv1 = (const float*)d_in[10]; const float* bv1 = (const float*)d_in[11];
    const float* Ws1 = (const float*)d_in[12]; const float* bs1 = (const float*)d_in[13];
    const float* Wq2 = (const float*)d_in[14]; const float* bq2 = (const float*)d_in[15];
    const float* Wk2 = (const float*)d_in[16]; const float* bk2 = (const float*)d_in[17];
    const float* Wv2 = (const float*)d_in[18]; const float* bv2 = (const float*)d_in[19];
    const float* Ws2 = (const float*)d_in[20]; const float* bs2 = (const float*)d_in[21];
    const float* Wf1 = (const float*)d_in[22]; const float* bf1 = (const float*)d_in[23];
    const float* Wf2 = (const float*)d_in[24]; const float* bf2 = (const float*)d_in[25];
    const float* Wf3 = (const float*)d_in[26]; const float* bf3 = (const float*)d_in[27];
    const float* Wf4 = (const float*)d_in[28]; const float* bf4 = (const float*)d_in[29];

    cudaFuncSetAttribute(mm_gemm, cudaFuncAttributeMaxDynamicSharedMemorySize, GSMEM);

    float *c2p, *f1p, *f2p, *f3p, *bc1p, *bc2p;
    __half *a1p, *a2p, *w1tp, *w2tp;
    cudaGetSymbolAddress((void**)&c2p, g_c2);
    cudaGetSymbolAddress((void**)&f1p, g_f1);
    cudaGetSymbolAddress((void**)&f2p, g_f2);
    cudaGetSymbolAddress((void**)&f3p, g_f3);
    cudaGetSymbolAddress((void**)&bc1p, g_bc1);
    cudaGetSymbolAddress((void**)&bc2p, g_bc2);
    cudaGetSymbolAddress((void**)&a1p, g_a1);
    cudaGetSymbolAddress((void**)&a2p, g_a2);
    cudaGetSymbolAddress((void**)&w1tp, g_w1t);
    cudaGetSymbolAddress((void**)&w2tp, g_w2t);

    k_cvt<<<256, 256>>>(ei, conn, bf1);
    k_scan<<<1, 1024>>>();
    k_fillb<<<(NEDGE + 255) / 256, 256>>>(bq1, bk1, bv1, bs1, bq2, bk2, bv2, bs2);
    k_pe<<<NP, 256>>>(x, npe, lpe, gpe);
    k_wsplit_all<<<dim3(64, 64, 5), dim3(32, 8)>>>(Wq1, Wk1, Wv1, Ws1, Wq2, Wk2, Wv2, Ws2);

    // conv1: fused 4-weight GEMM  [NP,2048] x [2048,8192], split-typed epilogue
    mm_gemm<<<dim3(NW1 / 128, NP / 128), 256, GSMEM>>>(a1p, w1tp, bc1p, (float*)0, 0, 1);

    k_att1<<<NN, 256>>>();

    // conv2: fused 4-weight GEMM  [NP,2048] x [2048,256]
    mm_gemm<<<dim3(NW2 / 128, NP / 128), 256, GSMEM>>>(a2p, w2tp, bc2p, c2p, NW2, 0);

    k_att2<<<NN, 64>>>();

    fc1s<<<FCK / FSLICE, 256>>>(Wf1);
    fc<<<NGRAPH, 128>>>(f1p, Wf2, bf2, f2p, 128, 256, 1, 1);
    fc<<<NGRAPH, 64>>>(f2p, Wf3, bf3, f3p, 64, 128, 1, 0);
    fc<<<NGRAPH, 32>>>(f3p, Wf4, bf4, (float*)d_out, OUTD, 64, 0, 0);
}

// round 16
// speedup vs baseline: 12.4728x; 1.1702x over previous
#include <cuda_runtime.h>
#include <cuda_fp16.h>
#include <cstdint>

#define NGRAPH 16
#define NODESP 420
#define NN     6720
#define NP     6784    // padded to 53*128
#define NEDGE  53760
#define INDIM  2048
#define C1     2048
#define H1     1024
#define H2     64
#define OUTD   18
#define FCK    26880
#define NW1    8192    // 4 fused conv1 weight mats
#define NW2    256     // 4 fused conv2 weight mats
#define KTOT   2048

// ======================= device scratch =======================
__device__ float  g_q1f[(size_t)NP * 2048];   // conv1 q (fp32)
__device__ float  g_s1f[(size_t)NP * 2048];   // conv1 skip (fp32)
__device__ __half g_kv1h[(size_t)NP * 4096];  // conv1 k|v (fp16)
__device__ float g_al1[NEDGE * 2];            // per-edge exp (spill)
__device__ float g_c2[(size_t)NP * NW2];      // fused q|k|v|s conv2 out
__device__ float g_out2[(size_t)NN * H2];
__device__ float g_al2[NEDGE];
__device__ float g_f1[NGRAPH * 256];
__device__ int   g_src[NEDGE];
__device__ int   g_dst[NEDGE];
__device__ int   g_conn[NN];
__device__ int   g_ofs[NN + 1];
__device__ int   g_wofs[NN];
__device__ int   g_eidx[NEDGE];
__device__ __half g_a1[(size_t)NP * INDIM];   // A1 fp16
__device__ __half g_a2[(size_t)NP * C1];      // A2 fp16
__device__ __half g_w1t[(size_t)NW1 * INDIM]; // W1^T fp16 [n][k]
__device__ __half g_w2t[(size_t)NW2 * C1];
__device__ float g_bc1[NW1];
__device__ float g_bc2[NW2];

// ======================= sm_80-baseline PTX wrappers =======================
__device__ __forceinline__ uint32_t smem_u32(const void* p) {
    uint32_t a;
    asm("{ .reg .u64 t; cvta.to.shared.u64 t, %1; cvt.u32.u64 %0, t; }" : "=r"(a) : "l"(p));
    return a;
}
__device__ __forceinline__ void cpa16(uint32_t s, const void* g) {
    asm volatile("cp.async.cg.shared.global [%0], [%1], 16;" :: "r"(s), "l"(g));
}
__device__ __forceinline__ void cpa_commit() {
    asm volatile("cp.async.commit_group;" ::: "memory");
}
__device__ __forceinline__ void cpa_wait2() {
    asm volatile("cp.async.wait_group 2;" ::: "memory");
}
__device__ __forceinline__ void ldsm4(uint32_t* r, uint32_t addr) {
    asm volatile("ldmatrix.sync.aligned.m8n8.x4.shared.b16 {%0,%1,%2,%3}, [%4];"
        : "=r"(r[0]), "=r"(r[1]), "=r"(r[2]), "=r"(r[3]) : "r"(addr));
}
__device__ __forceinline__ void mma16816(float* d, const uint32_t* a, const uint32_t* b) {
    asm volatile("mma.sync.aligned.m16n8k16.row.col.f32.f16.f16.f32 "
        "{%0,%1,%2,%3}, {%4,%5,%6,%7}, {%8,%9}, {%0,%1,%2,%3};"
        : "+f"(d[0]), "+f"(d[1]), "+f"(d[2]), "+f"(d[3])
        : "r"(a[0]), "r"(a[1]), "r"(a[2]), "r"(a[3]), "r"(b[0]), "r"(b[1]));
}

// ===== launch 1: index normalization + init (g_f1 seeded with bias) =====
__global__ void k_cvt(const int* __restrict__ ei, const int* __restrict__ conn,
                      const float* __restrict__ bf1) {
    bool is64 = true;
#pragma unroll
    for (int i = 0; i < 16; i++)
        if (ei[2 * i + 1] != 0) is64 = false;
    int t = blockIdx.x * blockDim.x + threadIdx.x;
    int stride = gridDim.x * blockDim.x;
    if (is64) {
        for (int i = t; i < NEDGE; i += stride) { g_src[i] = ei[2 * i]; g_dst[i] = ei[2 * (NEDGE + i)]; }
        for (int i = t; i < NN; i += stride) g_conn[i] = conn[2 * i];
    } else {
        for (int i = t; i < NEDGE; i += stride) { g_src[i] = ei[i]; g_dst[i] = ei[NEDGE + i]; }
        for (int i = t; i < NN; i += stride) g_conn[i] = conn[i];
    }
    for (int i = t; i < NGRAPH * 256; i += stride) g_f1[i] = bf1[i & 255];
    // pad rows NN..NP of conv2 input must stay zero
    const __half z = __float2half(0.f);
    for (size_t j = (size_t)NN * C1 + t; j < (size_t)NP * C1; j += stride)
        g_a2[j] = z;
}

// ===== launch 2: smem histogram + scan -> CSR offsets =====
__global__ void k_scan() {
    __shared__ int scnt[NN];
    __shared__ int sh[1024];
    int t = threadIdx.x;
    for (int i = t; i < NN; i += 1024) scnt[i] = 0;
    __syncthreads();
    for (int e = t; e < NEDGE; e += 1024) atomicAdd(&scnt[g_dst[e]], 1);
    __syncthreads();
    int base = t * 7;
    int loc[7];
    int s = 0;
#pragma unroll
    for (int i = 0; i < 7; i++) {
        int n = base + i;
        int c = (n < NN) ? scnt[n] : 0;
        loc[i] = s;
        s += c;
    }
    sh[t] = s;
    __syncthreads();
    for (int off = 1; off < 1024; off <<= 1) {
        int v = (t >= off) ? sh[t - off] : 0;
        __syncthreads();
        sh[t] += v;
        __syncthreads();
    }
    int ex0 = sh[t] - s;
#pragma unroll
    for (int i = 0; i < 7; i++) {
        int n = base + i;
        if (n < NN) {
            g_ofs[n] = ex0 + loc[i];
            g_wofs[n] = ex0 + loc[i];
        }
    }
    if (t == 0) g_ofs[NN] = NEDGE;
}

// ===== launch 3: CSR fill + fused bias packing =====
__global__ void k_fillb(const float* b0, const float* b1, const float* b2, const float* b3,
                        const float* c0, const float* c1_, const float* c2, const float* c3) {
    int e = blockIdx.x * blockDim.x + threadIdx.x;
    if (e < NEDGE) {
        int pos = atomicAdd(&g_wofs[g_dst[e]], 1);
        g_eidx[pos] = e;
    }
    if (e < NW1) {
        int w = e >> 11, j = e & 2047;
        g_bc1[e] = (w == 0 ? b0 : w == 1 ? b1 : w == 2 ? b2 : b3)[j];
    }
    if (e < NW2) {
        int w = e >> 6, j = e & 63;
        g_bc2[e] = (w == 0 ? c0 : w == 1 ? c1_ : w == 2 ? c2 : c3)[j];
    }
}

// ===== launch 4: PE add -> fp16 A1 =====
__global__ void k_pe(const float* __restrict__ x, const float* __restrict__ npe,
                     const float* __restrict__ lpe, const float* __restrict__ gpe) {
    int node = blockIdx.x;
    __half* a1 = g_a1 + (size_t)node * INDIM;
    if (node >= NN) {
        for (int j = threadIdx.x; j < INDIM / 2; j += blockDim.x)
            ((uint32_t*)a1)[j] = 0u;
        return;
    }
    int lobe = g_conn[node] - 1;
    int lung = (lobe <= 1) ? 0 : 1;
    const float4* xp = (const float4*)(x + (size_t)node * INDIM);
    const float4* np = (const float4*)(npe + (size_t)(node % NODESP) * INDIM);
    const float4* lp = (const float4*)(lpe + (size_t)lobe * INDIM);
    const float4* gp = (const float4*)(gpe + (size_t)lung * INDIM);
    for (int j = threadIdx.x; j < INDIM / 4; j += blockDim.x) {
        float4 a = xp[j], b = np[j], c = lp[j], d = gp[j];
        float v[4] = { a.x + b.x + c.x + d.x, a.y + b.y + c.y + d.y,
                       a.z + b.z + c.z + d.z, a.w + b.w + c.w + d.w };
        ((__half2*)a1)[2 * j]     = __halves2half2(__float2half_rn(v[0]), __float2half_rn(v[1]));
        ((__half2*)a1)[2 * j + 1] = __halves2half2(__float2half_rn(v[2]), __float2half_rn(v[3]));
    }
}

// ===== launch 5: fused weight transpose -> fp16 (all 8 matrices) =====
__global__ void k_wsplit_all(const float* Wq1, const float* Wk1, const float* Wv1, const float* Ws1,
                             const float* Wq2, const float* Wk2, const float* Wv2, const float* Ws2) {
    __shared__ float tile[32][33];
    int z = blockIdx.z;
    const float* W;
    __half* T;
    int Nw, K, n0, noff;
    if (z < 4) {
        W = (z == 0) ? Wq1 : (z == 1) ? Wk1 : (z == 2) ? Wv1 : Ws1;
        T = g_w1t; Nw = C1; K = INDIM;
        n0 = blockIdx.x * 32; noff = z * 2048;
    } else {
        if (blockIdx.x >= 8) return;
        int mat = blockIdx.x >> 1;
        W = (mat == 0) ? Wq2 : (mat == 1) ? Wk2 : (mat == 2) ? Wv2 : Ws2;
        T = g_w2t; Nw = H2; K = C1;
        n0 = (blockIdx.x & 1) * 32; noff = mat * 64;
    }
    int k0 = blockIdx.y * 32;
    int tx = threadIdx.x, ty = threadIdx.y;  // 32 x 8
#pragma unroll
    for (int r = 0; r < 4; r++)
        tile[ty + r * 8][tx] = W[(size_t)(k0 + ty + r * 8) * Nw + n0 + tx];
    __syncthreads();
#pragma unroll
    for (int r = 0; r < 4; r++) {
        int n = n0 + ty + r * 8;
        T[(size_t)(noff + n) * K + k0 + tx] = __float2half_rn(tile[tx][ty + r * 8]);
    }
}

// ======================= mma.sync fp16 GEMM (single term) =======================
// mode 0: C[m][n] = sum + bias[n] (fp32, ldc)
// mode 1: conv1 layout: cols [0,2048)->g_q1f fp32, [2048,6144)->g_kv1h fp16, [6144,8192)->g_s1f fp32
#define ASTAGE 16384
#define STAGE  32768
#define GSMEM  (3 * STAGE)
#define NCHUNK (KTOT / 64)

__device__ __forceinline__ uint32_t swz(int row, int ch) {
    return (uint32_t)(row * 128 + ((ch ^ (row & 7)) << 4));
}

__device__ __forceinline__ void load_stage(uint32_t sbase, int tid, int s, int c,
        const __half* __restrict__ A, const __half* __restrict__ B, int m0, int n0) {
    uint32_t sa = sbase + s * STAGE;
    uint32_t sb = sa + ASTAGE;
    int k0 = c * 64;
#pragma unroll
    for (int i = 0; i < 4; i++) {
        int idx = tid + i * 256;
        int r = idx >> 3, ch = idx & 7;
        cpa16(sa + swz(r, ch), A + (size_t)(m0 + r) * KTOT + k0 + ch * 8);
    }
#pragma unroll
    for (int i = 0; i < 4; i++) {
        int idx = tid + i * 256;
        int r = idx >> 3, ch = idx & 7;
        cpa16(sb + swz(r, ch), B + (size_t)(n0 + r) * KTOT + k0 + ch * 8);
    }
    cpa_commit();
}

__global__ void __launch_bounds__(256, 2) mm_gemm(
        const __half* __restrict__ A, const __half* __restrict__ B,
        const float* __restrict__ bias, float* __restrict__ C, int ldc, int mode) {
    extern __shared__ char smem[];
    uint32_t sbase = smem_u32(smem);
    int tid = threadIdx.x, lane = tid & 31, wid = tid >> 5;
    int wm = wid >> 2, wn = wid & 3;
    int m0 = blockIdx.y * 128, n0 = blockIdx.x * 128;

    float acc[4][4][4];
#pragma unroll
    for (int i = 0; i < 4; i++)
#pragma unroll
        for (int j = 0; j < 4; j++)
#pragma unroll
            for (int q = 0; q < 4; q++) acc[i][j][q] = 0.f;

    load_stage(sbase, tid, 0, 0, A, B, m0, n0);
    load_stage(sbase, tid, 1, 1, A, B, m0, n0);
    load_stage(sbase, tid, 2, 2, A, B, m0, n0);

    int a_row_l = (lane & 15);
    int a_chl   = (lane >> 4);
    int b_row_l = (lane & 7) + ((lane >> 4) << 3);
    int b_chl   = ((lane >> 3) & 1);

    for (int c = 0; c < NCHUNK; c++) {
        cpa_wait2();
        __syncthreads();
        uint32_t sa = sbase + (c % 3) * STAGE;
        uint32_t sb = sa + ASTAGE;
#pragma unroll
        for (int ks = 0; ks < 4; ks++) {
            uint32_t a_f[4][4], b_f[2][4];
#pragma unroll
            for (int mt = 0; mt < 4; mt++) {
                int row = wm * 64 + mt * 16 + a_row_l;
                ldsm4(a_f[mt], sa + swz(row, ks * 2 + a_chl));
            }
#pragma unroll
            for (int np = 0; np < 2; np++) {
                int row = wn * 32 + np * 16 + b_row_l;
                ldsm4(b_f[np], sb + swz(row, ks * 2 + b_chl));
            }
#pragma unroll
            for (int mt = 0; mt < 4; mt++)
#pragma unroll
                for (int nt = 0; nt < 4; nt++)
                    mma16816(acc[mt][nt], a_f[mt], &b_f[nt >> 1][(nt & 1) * 2]);
        }
        __syncthreads();
        if (c + 3 < NCHUNK)
            load_stage(sbase, tid, (c + 3) % 3, c + 3, A, B, m0, n0);
        else
            cpa_commit();
    }

#pragma unroll
    for (int mt = 0; mt < 4; mt++) {
        int row = m0 + wm * 64 + mt * 16 + (lane >> 2);
#pragma unroll
        for (int nt = 0; nt < 4; nt++) {
            int cg = n0 + wn * 32 + nt * 8 + (lane & 3) * 2;
            float b0 = bias[cg], b1 = bias[cg + 1];
            float v00 = acc[mt][nt][0] + b0, v01 = acc[mt][nt][1] + b1;
            float v10 = acc[mt][nt][2] + b0, v11 = acc[mt][nt][3] + b1;
            if (mode == 0) {
                float* p0 = C + (size_t)row * ldc + cg;
                p0[0] = v00; p0[1] = v01;
                float* p1 = p0 + 8 * ldc;
                p1[0] = v10; p1[1] = v11;
            } else if (cg < 2048) {
                float* p0 = g_q1f + (size_t)row * 2048 + cg;
                p0[0] = v00; p0[1] = v01;
                p0 += 8 * 2048;
                p0[0] = v10; p0[1] = v11;
            } else if (cg < 6144) {
                __half* p0 = g_kv1h + (size_t)row * 4096 + (cg - 2048);
                *(__half2*)p0 = __floats2half2_rn(v00, v01);
                *(__half2*)(p0 + 8 * 4096) = __floats2half2_rn(v10, v11);
            } else {
                float* p0 = g_s1f + (size_t)row * 2048 + (cg - 6144);
                p0[0] = v00; p0[1] = v01;
                p0 += 8 * 2048;
                p0[0] = v10; p0[1] = v11;
            }
        }
    }
}

// ======================= fused conv1 attention (CSR, no atomics) =======================
// q: g_q1f [node][2048] fp32; k|v: g_kv1h [node][4096] fp16 (k 0..2047, v 2048..4095);
// skip: g_s1f [node][2048] fp32. Thread t owns cols t*8..t*8+7 (head = t>>7).
__global__ void __launch_bounds__(256) k_att1() {
    __shared__ float s_part[32][8];
    __shared__ float s_den[2];
    int node = blockIdx.x;
    int tid = threadIdx.x, lane = tid & 31, wid = tid >> 5;
    int tcol = tid * 8;
    int head = tid >> 7;
    int ofs = g_ofs[node], nE = g_ofs[node + 1] - ofs;

    if (tid < 2) s_den[tid] = 0.f;

    float qreg[8];
    const float4* qp = (const float4*)(g_q1f + (size_t)node * 2048 + tcol);
    *(float4*)&qreg[0] = qp[0];
    *(float4*)&qreg[4] = qp[1];
    __syncthreads();

    for (int t0 = 0; t0 < nE; t0 += 32) {
        int tE = min(32, nE - t0);
        for (int e = 0; e < tE; e++) {
            int eid = g_eidx[ofs + t0 + e];
            int src = g_src[eid];
            union { uint4 u; __half2 h[4]; } K;
            K.u = *(const uint4*)(g_kv1h + (size_t)src * 4096 + tcol);
            float2 k0 = __half22float2(K.h[0]), k1 = __half22float2(K.h[1]);
            float2 k2 = __half22float2(K.h[2]), k3 = __half22float2(K.h[3]);
            float p = qreg[0] * k0.x + qreg[1] * k0.y + qreg[2] * k1.x + qreg[3] * k1.y
                    + qreg[4] * k2.x + qreg[5] * k2.y + qreg[6] * k3.x + qreg[7] * k3.y;
#pragma unroll
            for (int off = 16; off; off >>= 1) p += __shfl_xor_sync(0xffffffffu, p, off);
            if (lane == 0) s_part[e][wid] = p;
        }
        __syncthreads();
        if (tid < tE * 2) {
            int e = tid >> 1, h = tid & 1;
            float d = s_part[e][h * 4 + 0] + s_part[e][h * 4 + 1]
                    + s_part[e][h * 4 + 2] + s_part[e][h * 4 + 3];
            float ex = expf(d * (1.f / 32.f));   // softmax shift-invariant, alpha O(1)
            int eid = g_eidx[ofs + t0 + e];
            g_al1[eid * 2 + h] = ex;
            atomicAdd(&s_den[h], ex);
        }
        __syncthreads();
    }

    float invd = 1.f / (s_den[head] + 1e-16f);

    float acc[8] = {0.f, 0.f, 0.f, 0.f, 0.f, 0.f, 0.f, 0.f};
    for (int i = 0; i < nE; i++) {
        int eid = g_eidx[ofs + i];
        int src = g_src[eid];
        float a = g_al1[eid * 2 + head] * invd;
        union { uint4 u; __half2 h[4]; } V;
        V.u = *(const uint4*)(g_kv1h + (size_t)src * 4096 + 2048 + tcol);
        float2 v0 = __half22float2(V.h[0]), v1 = __half22float2(V.h[1]);
        float2 v2 = __half22float2(V.h[2]), v3 = __half22float2(V.h[3]);
        acc[0] += a * v0.x; acc[1] += a * v0.y; acc[2] += a * v1.x; acc[3] += a * v1.y;
        acc[4] += a * v2.x; acc[5] += a * v2.y; acc[6] += a * v3.x; acc[7] += a * v3.y;
    }

    const float4* sp = (const float4*)(g_s1f + (size_t)node * 2048 + tcol);
    float4 s0 = sp[0], s1 = sp[1];
    float skip[8] = {s0.x, s0.y, s0.z, s0.w, s1.x, s1.y, s1.z, s1.w};
    union { __half b[8]; uint4 u; } H;
#pragma unroll
    for (int j = 0; j < 8; j++)
        H.b[j] = __float2half_rn(fmaxf(acc[j] + skip[j], 0.f));
    *(uint4*)(g_a2 + (size_t)node * C1 + tcol) = H.u;
}

// ======================= fused conv2 attention (CSR, no atomics) =======================
__global__ void __launch_bounds__(64) k_att2() {
    __shared__ float s_part[32][2];
    __shared__ float s_den;
    int node = blockIdx.x;
    int tid = threadIdx.x, lane = tid & 31, wid = tid >> 5;
    int ofs = g_ofs[node], nE = g_ofs[node + 1] - ofs;

    if (tid == 0) s_den = 0.f;
    float qreg = g_c2[(size_t)node * NW2 + tid];
    __syncthreads();

    for (int t0 = 0; t0 < nE; t0 += 32) {
        int tE = min(32, nE - t0);
        for (int e = 0; e < tE; e++) {
            int eid = g_eidx[ofs + t0 + e];
            int src = g_src[eid];
            float p = qreg * g_c2[(size_t)src * NW2 + 64 + tid];
#pragma unroll
            for (int off = 16; off; off >>= 1) p += __shfl_xor_sync(0xffffffffu, p, off);
            if (lane == 0) s_part[e][wid] = p;
        }
        __syncthreads();
        if (tid < tE) {
            float d = s_part[tid][0] + s_part[tid][1];
            float ex = expf(d * 0.125f);
            g_al2[g_eidx[ofs + t0 + tid]] = ex;
            atomicAdd(&s_den, ex);
        }
        __syncthreads();
    }

    float invd = 1.f / (s_den + 1e-16f);
    float acc = 0.f;
    for (int i = 0; i < nE; i++) {
        int eid = g_eidx[ofs + i];
        int src = g_src[eid];
        acc += g_al2[eid] * invd * g_c2[(size_t)src * NW2 + 128 + tid];
    }
    float skip = g_c2[(size_t)node * NW2 + 192 + tid];
    g_out2[(size_t)node * H2 + tid] = fmaxf(acc + skip, 0.f);
}

// ======================= FC head =======================
// fc1: k-sliced, W read ONCE; partials accumulated into bias-seeded g_f1.
#define FSLICE 240
__global__ void __launch_bounds__(256) fc1s(const float* __restrict__ W) {
    __shared__ float a_s[FSLICE][17];   // pad 17 kills 16-way store conflict
    int k0 = blockIdx.x * FSLICE;
    int n = threadIdx.x;
    if (n < FSLICE) {
#pragma unroll
        for (int g = 0; g < NGRAPH; g++)
            a_s[n][g] = g_out2[(size_t)g * FCK + k0 + n];
    }
    __syncthreads();
    float acc[NGRAPH];
#pragma unroll
    for (int g = 0; g < NGRAPH; g++) acc[g] = 0.f;
    for (int k = 0; k < FSLICE; k++) {
        float w = W[(size_t)(k0 + k) * 256 + n];
#pragma unroll
        for (int g = 0; g < NGRAPH; g++)
            acc[g] = fmaf(a_s[k][g], w, acc[g]);
    }
#pragma unroll
    for (int g = 0; g < NGRAPH; g++)
        atomicAdd(&g_f1[g * 256 + n], acc[g]);
}

// fused fc2+fc3+fc4: one block per graph, 128 threads
__global__ void __launch_bounds__(128) k_fchead(
        const float* __restrict__ W2, const float* __restrict__ b2,
        const float* __restrict__ W3, const float* __restrict__ b3,
        const float* __restrict__ W4, const float* __restrict__ b4,
        float* __restrict__ out) {
    __shared__ float s1[256], s2[128], s3[64];
    int g = blockIdx.x, t = threadIdx.x;
    s1[t]       = fmaxf(g_f1[g * 256 + t], 0.f);
    s1[t + 128] = fmaxf(g_f1[g * 256 + t + 128], 0.f);
    __syncthreads();
    float a = b2[t];
    for (int k = 0; k < 256; k++) a = fmaf(s1[k], W2[(size_t)k * 128 + t], a);
    s2[t] = fmaxf(a, 0.f);
    __syncthreads();
    if (t < 64) {
        a = b3[t];
        for (int k = 0; k < 128; k++) a = fmaf(s2[k], W3[(size_t)k * 64 + t], a);
        s3[t] = fmaxf(a, 0.f);
    }
    __syncthreads();
    if (t < OUTD) {
        a = b4[t];
        for (int k = 0; k < 64; k++) a = fmaf(s3[k], W4[(size_t)k * OUTD + t], a);
        out[g * OUTD + t] = a;
    }
}

// ======================= launch =======================
extern "C" void kernel_launch(void* const* d_in, const int* in_sizes, int n_in,
                              void* d_out, int out_size) {
    const float* x = (const float*)d_in[0];
    const int* ei = (const int*)d_in[1];
    const int* conn = (const int*)d_in[2];
    const float* npe = (const float*)d_in[3];
    const float* lpe = (const float*)d_in[4];
    const float* gpe = (const float*)d_in[5];
    const float* Wq1 = (const float*)d_in[6];  const float* bq1 = (const float*)d_in[7];
    const float* Wk1 = (const float*)d_in[8];  const float* bk1 = (const float*)d_in[9];
    const float* Wv1 = (const float*)d_in[10]; const float* bv1 = (const float*)d_in[11];
    const float* Ws1 = (const float*)d_in[12]; const float* bs1 = (const float*)d_in[13];
    const float* Wq2 = (const float*)d_in[14]; const float* bq2 = (const float*)d_in[15];
    const float* Wk2 = (const float*)d_in[16]; const float* bk2 = (const float*)d_in[17];
    const float* Wv2 = (const float*)d_in[18]; const float* bv2 = (const float*)d_in[19];
    const float* Ws2 = (const float*)d_in[20]; const float* bs2 = (const float*)d_in[21];
    const float* Wf1 = (const float*)d_in[22]; const float* bf1 = (const float*)d_in[23];
    const float* Wf2 = (const float*)d_in[24]; const float* bf2 = (const float*)d_in[25];
    const float* Wf3 = (const float*)d_in[26]; const float* bf3 = (const float*)d_in[27];
    const float* Wf4 = (const float*)d_in[28]; const float* bf4 = (const float*)d_in[29];

    cudaFuncSetAttribute(mm_gemm, cudaFuncAttributeMaxDynamicSharedMemorySize, GSMEM);

    float *c2p, *f1p, *bc1p, *bc2p;
    __half *a1p, *a2p, *w1tp, *w2tp;
    cudaGetSymbolAddress((void**)&c2p, g_c2);
    cudaGetSymbolAddress((void**)&f1p, g_f1);
    cudaGetSymbolAddress((void**)&bc1p, g_bc1);
    cudaGetSymbolAddress((void**)&bc2p, g_bc2);
    cudaGetSymbolAddress((void**)&a1p, g_a1);
    cudaGetSymbolAddress((void**)&a2p, g_a2);
    cudaGetSymbolAddress((void**)&w1tp, g_w1t);
    cudaGetSymbolAddress((void**)&w2tp, g_w2t);

    k_cvt<<<256, 256>>>(ei, conn, bf1);
    k_scan<<<1, 1024>>>();
    k_fillb<<<(NEDGE + 255) / 256, 256>>>(bq1, bk1, bv1, bs1, bq2, bk2, bv2, bs2);
    k_pe<<<NP, 256>>>(x, npe, lpe, gpe);
    k_wsplit_all<<<dim3(64, 64, 5), dim3(32, 8)>>>(Wq1, Wk1, Wv1, Ws1, Wq2, Wk2, Wv2, Ws2);

    // conv1: fused 4-weight GEMM  [NP,2048] x [2048,8192], split-typed epilogue
    mm_gemm<<<dim3(NW1 / 128, NP / 128), 256, GSMEM>>>(a1p, w1tp, bc1p, (float*)0, 0, 1);

    k_att1<<<NN, 256>>>();

    // conv2: fused 4-weight GEMM  [NP,2048] x [2048,256]
    mm_gemm<<<dim3(NW2 / 128, NP / 128), 256, GSMEM>>>(a2p, w2tp, bc2p, c2p, NW2, 0);

    k_att2<<<NN, 64>>>();

    fc1s<<<FCK / FSLICE, 256>>>(Wf1);
    k_fchead<<<NGRAPH, 128>>>(Wf2, bf2, Wf3, bf3, Wf4, bf4, (float*)d_out);
}